// round 1
// baseline (speedup 1.0000x reference)
#include <cuda_runtime.h>
#include <float.h>
#include <math.h>

// Problem constants
#define BSZ   2
#define NN    1024
#define EE    2048
#define LTOT  3072          // NN + EE
#define DIMN  128
#define EDIM  256
#define HEADS 8
#define DHEAD 64
#define INNER 512           // HEADS*DHEAD
#define SCALE 0.125f        // DHEAD^-0.5

// Scratch (static device arrays; allocation is forbidden)
__device__ float g_q[BSZ * HEADS * LTOT * DHEAD];
__device__ float g_k[BSZ * HEADS * LTOT * DHEAD];
__device__ float g_v[BSZ * HEADS * LTOT * DHEAD];
__device__ float g_o[BSZ * LTOT * INNER];
__device__ int   g_mask[BSZ * LTOT];

// ---------------------------------------------------------------------------
// Mask decode: bool serialization width is unknown (1-byte vs 4-byte).
// Heuristic: count nonzero bytes among the first 6144 bytes. If elements are
// 1 byte (p~0.5 true) expect ~3072 nonzero bytes; if 4 bytes (int 0/1 or
// float 0.0/1.0) expect <=1536. Threshold at 2304. Deterministic.
// ---------------------------------------------------------------------------
__global__ void decode_mask_kernel(const unsigned char* __restrict__ raw) {
    __shared__ int partial[256];
    const int n = BSZ * LTOT;
    int tid = threadIdx.x;
    int cnt = 0;
    for (int i = tid; i < n; i += 256) cnt += (raw[i] != 0);
    partial[tid] = cnt;
    __syncthreads();
    for (int s = 128; s > 0; s >>= 1) {
        if (tid < s) partial[tid] += partial[tid + s];
        __syncthreads();
    }
    int width1 = partial[0] > (n * 3 / 8);
    const int* raw32 = (const int*)raw;
    for (int i = tid; i < n; i += 256)
        g_mask[i] = width1 ? (raw[i] != 0) : (raw32[i] != 0);
}

// ---------------------------------------------------------------------------
// Generic GEMM: C[M,Ncols] = A' @ W + bias, with source-row remapping and
// two destination modes.
//   source row: m -> b = m/rowsPerBatch, r = m%rowsPerBatch,
//               aRow = b*aBatchStride + aSeqOff + r   (lda = K)
//   dstMode 0 : scatter into [B,H,LTOT,DHEAD]: c -> (h,d), l = dstSeqOff + r
//   dstMode 1 : dst[m*Ncols + c]
// 64x64 tile, 256 threads, 4x4 per thread, K-step 16.
// ---------------------------------------------------------------------------
__global__ void gemm_kernel(const float* __restrict__ A,
                            const float* __restrict__ W,
                            const float* __restrict__ bias,
                            float* __restrict__ dst,
                            int M, int K, int Ncols,
                            int rowsPerBatch, int aBatchStride, int aSeqOff,
                            int dstMode, int dstSeqOff) {
    __shared__ float sA[64 * 17];
    __shared__ float sW[16 * 64];

    int tid = threadIdx.x;
    int tx = tid & 15, ty = tid >> 4;
    int row0 = blockIdx.y * 64;
    int col0 = blockIdx.x * 64;

    float acc[4][4] = {};

    for (int kt = 0; kt < K; kt += 16) {
        #pragma unroll
        for (int t = 0; t < 4; t++) {
            int idx = tid + t * 256;         // 0..1023 over 64x16 A tile
            int i = idx >> 4, kk = idx & 15;
            int m = row0 + i;
            int b = m / rowsPerBatch;
            int r = m - b * rowsPerBatch;
            sA[i * 17 + kk] = A[(b * aBatchStride + aSeqOff + r) * K + kt + kk];
        }
        #pragma unroll
        for (int t = 0; t < 4; t++) {
            int idx = tid + t * 256;         // 0..1023 over 16x64 W tile
            int kk = idx >> 6, j = idx & 63;
            sW[kk * 64 + j] = W[(kt + kk) * Ncols + col0 + j];
        }
        __syncthreads();

        #pragma unroll
        for (int kk = 0; kk < 16; kk++) {
            const float4 w4 = *(const float4*)&sW[kk * 64 + tx * 4];
            float a0 = sA[(ty * 4 + 0) * 17 + kk];
            float a1 = sA[(ty * 4 + 1) * 17 + kk];
            float a2 = sA[(ty * 4 + 2) * 17 + kk];
            float a3 = sA[(ty * 4 + 3) * 17 + kk];
            acc[0][0] += a0 * w4.x; acc[0][1] += a0 * w4.y; acc[0][2] += a0 * w4.z; acc[0][3] += a0 * w4.w;
            acc[1][0] += a1 * w4.x; acc[1][1] += a1 * w4.y; acc[1][2] += a1 * w4.z; acc[1][3] += a1 * w4.w;
            acc[2][0] += a2 * w4.x; acc[2][1] += a2 * w4.y; acc[2][2] += a2 * w4.z; acc[2][3] += a2 * w4.w;
            acc[3][0] += a3 * w4.x; acc[3][1] += a3 * w4.y; acc[3][2] += a3 * w4.z; acc[3][3] += a3 * w4.w;
        }
        __syncthreads();
    }

    #pragma unroll
    for (int a = 0; a < 4; a++) {
        int m = row0 + ty * 4 + a;
        int b = m / rowsPerBatch;
        int r = m - b * rowsPerBatch;
        #pragma unroll
        for (int bb = 0; bb < 4; bb++) {
            int c = col0 + tx * 4 + bb;
            float val = acc[a][bb] + bias[c];
            if (dstMode == 0) {
                int h = c >> 6, d = c & 63;
                dst[(((b * HEADS + h) * LTOT) + dstSeqOff + r) * DHEAD + d] = val;
            } else {
                dst[m * Ncols + c] = val;
            }
        }
    }
}

// ---------------------------------------------------------------------------
// Flash attention, fp32. Block = 64 query rows for one (b,h). 256 threads as
// 16x16, 4x4 register tile. Online softmax with -FLT_MAX masking, matching
// the reference exactly (fully-masked rows -> uniform distribution).
// Dynamic smem: Qs[64][65], Ks[64][65] (reused as P), Vs[64][65].
// ---------------------------------------------------------------------------
__global__ void attn_kernel() {
    extern __shared__ float sm[];
    float* Qs = sm;                     // 64*65
    float* Ks = sm + 64 * 65;           // 64*65, reused as P after S compute
    float* Vs = sm + 2 * 64 * 65;       // 64*65
    __shared__ float m_s[64], l_s[64], c_s[64];
    __shared__ int qm_s[64], km_s[64];

    int tid = threadIdx.x;
    int tx = tid & 15, ty = tid >> 4;
    int bh = blockIdx.y;                // b*HEADS + h
    int b  = bh >> 3;
    int h  = bh & 7;
    int q0 = blockIdx.x * 64;

    const float* Qg = g_q + (size_t)bh * LTOT * DHEAD;
    const float* Kg = g_k + (size_t)bh * LTOT * DHEAD;
    const float* Vg = g_v + (size_t)bh * LTOT * DHEAD;

    for (int idx = tid; idx < 64 * 64; idx += 256) {
        int i = idx >> 6, d = idx & 63;
        Qs[i * 65 + d] = Qg[(q0 + i) * DHEAD + d] * SCALE;  // pre-scale Q
    }
    if (tid < 64) {
        qm_s[tid] = g_mask[b * LTOT + q0 + tid];
        m_s[tid] = -FLT_MAX;
        l_s[tid] = 0.f;
    }
    __syncthreads();

    int qm[4];
    #pragma unroll
    for (int a = 0; a < 4; a++) qm[a] = qm_s[ty * 4 + a];

    float o[4][4] = {};

    for (int k0 = 0; k0 < LTOT; k0 += 64) {
        // Load K,V tiles (coalesced)
        for (int idx = tid; idx < 64 * 64; idx += 256) {
            int j = idx >> 6, d = idx & 63;
            Ks[j * 65 + d] = Kg[(k0 + j) * DHEAD + d];
            Vs[j * 65 + d] = Vg[(k0 + j) * DHEAD + d];
        }
        if (tid < 64) km_s[tid] = g_mask[b * LTOT + k0 + tid];
        __syncthreads();

        // S = Q @ K^T (Q pre-scaled)
        float s[4][4] = {};
        #pragma unroll 8
        for (int d = 0; d < 64; d++) {
            float qa0 = Qs[(ty * 4 + 0) * 65 + d];
            float qa1 = Qs[(ty * 4 + 1) * 65 + d];
            float qa2 = Qs[(ty * 4 + 2) * 65 + d];
            float qa3 = Qs[(ty * 4 + 3) * 65 + d];
            float kb0 = Ks[(tx * 4 + 0) * 65 + d];
            float kb1 = Ks[(tx * 4 + 1) * 65 + d];
            float kb2 = Ks[(tx * 4 + 2) * 65 + d];
            float kb3 = Ks[(tx * 4 + 3) * 65 + d];
            s[0][0] += qa0 * kb0; s[0][1] += qa0 * kb1; s[0][2] += qa0 * kb2; s[0][3] += qa0 * kb3;
            s[1][0] += qa1 * kb0; s[1][1] += qa1 * kb1; s[1][2] += qa1 * kb2; s[1][3] += qa1 * kb3;
            s[2][0] += qa2 * kb0; s[2][1] += qa2 * kb1; s[2][2] += qa2 * kb2; s[2][3] += qa2 * kb3;
            s[3][0] += qa3 * kb0; s[3][1] += qa3 * kb1; s[3][2] += qa3 * kb2; s[3][3] += qa3 * kb3;
        }

        // Mask (same semantics as reference: -FLT_MAX where either side masked)
        int km[4];
        #pragma unroll
        for (int bb = 0; bb < 4; bb++) km[bb] = km_s[tx * 4 + bb];
        #pragma unroll
        for (int a = 0; a < 4; a++)
            #pragma unroll
            for (int bb = 0; bb < 4; bb++)
                if (!(qm[a] & km[bb])) s[a][bb] = -FLT_MAX;

        // Row max across the 16-lane tx group
        float rmax[4];
        #pragma unroll
        for (int a = 0; a < 4; a++) {
            float mx = fmaxf(fmaxf(s[a][0], s[a][1]), fmaxf(s[a][2], s[a][3]));
            #pragma unroll
            for (int off = 8; off >= 1; off >>= 1)
                mx = fmaxf(mx, __shfl_xor_sync(0xffffffffu, mx, off));
            rmax[a] = mx;
        }
        if (tx == 0) {
            #pragma unroll
            for (int a = 0; a < 4; a++) {
                int row = ty * 4 + a;
                float mo = m_s[row];
                float mn = fmaxf(mo, rmax[a]);
                c_s[row] = __expf(mo - mn);   // 1 if both -FLT_MAX; 0 if new finite max
                m_s[row] = mn;
            }
        }
        __syncthreads();   // all lanes done reading Ks; m_s/c_s visible

        // P = exp(S - m); store into Ks buffer; accumulate row sums
        float rsum[4];
        #pragma unroll
        for (int a = 0; a < 4; a++) {
            int row = ty * 4 + a;
            float mrow = m_s[row];
            float acc = 0.f;
            #pragma unroll
            for (int bb = 0; bb < 4; bb++) {
                float p = __expf(s[a][bb] - mrow);
                Ks[row * 65 + tx * 4 + bb] = p;
                acc += p;
            }
            rsum[a] = acc;
        }
        #pragma unroll
        for (int a = 0; a < 4; a++) {
            #pragma unroll
            for (int off = 8; off >= 1; off >>= 1)
                rsum[a] += __shfl_xor_sync(0xffffffffu, rsum[a], off);
        }
        if (tx == 0) {
            #pragma unroll
            for (int a = 0; a < 4; a++) {
                int row = ty * 4 + a;
                l_s[row] = l_s[row] * c_s[row] + rsum[a];
            }
        }

        // Rescale accumulators by correction factor
        #pragma unroll
        for (int a = 0; a < 4; a++) {
            float c = c_s[ty * 4 + a];
            #pragma unroll
            for (int bb = 0; bb < 4; bb++) o[a][bb] *= c;
        }
        __syncwarp();   // P rows for this ty group produced within this warp

        // O += P @ V
        #pragma unroll 4
        for (int j = 0; j < 64; j++) {
            float p0 = Ks[(ty * 4 + 0) * 65 + j];
            float p1 = Ks[(ty * 4 + 1) * 65 + j];
            float p2 = Ks[(ty * 4 + 2) * 65 + j];
            float p3 = Ks[(ty * 4 + 3) * 65 + j];
            float v0 = Vs[j * 65 + tx * 4 + 0];
            float v1 = Vs[j * 65 + tx * 4 + 1];
            float v2 = Vs[j * 65 + tx * 4 + 2];
            float v3 = Vs[j * 65 + tx * 4 + 3];
            o[0][0] += p0 * v0; o[0][1] += p0 * v1; o[0][2] += p0 * v2; o[0][3] += p0 * v3;
            o[1][0] += p1 * v0; o[1][1] += p1 * v1; o[1][2] += p1 * v2; o[1][3] += p1 * v3;
            o[2][0] += p2 * v0; o[2][1] += p2 * v1; o[2][2] += p2 * v2; o[2][3] += p2 * v3;
            o[3][0] += p3 * v0; o[3][1] += p3 * v1; o[3][2] += p3 * v2; o[3][3] += p3 * v3;
        }
        __syncthreads();   // before next tile overwrites Ks/Vs
    }

    // Normalize and write out in [B, LTOT, INNER] layout for output GEMMs
    #pragma unroll
    for (int a = 0; a < 4; a++) {
        int row = ty * 4 + a;
        float inv = 1.f / l_s[row];
        #pragma unroll
        for (int bb = 0; bb < 4; bb++) {
            g_o[((size_t)(b * LTOT + q0 + row)) * INNER + h * DHEAD + tx * 4 + bb] =
                o[a][bb] * inv;
        }
    }
}

// ---------------------------------------------------------------------------
// kernel_launch
// Input order: nodes, edges, mask, Wq,bq, Wk,bk, Wv,bv, Weq,beq, Wek,bek,
//              Wev,bev, Wo,bo, Weo,beo
// Output: node_out [2,1024,128] then edge_out [2,2048,256], fp32.
// ---------------------------------------------------------------------------
extern "C" void kernel_launch(void* const* d_in, const int* in_sizes, int n_in,
                              void* d_out, int out_size) {
    const float* nodes = (const float*)d_in[0];
    const float* edges = (const float*)d_in[1];
    const unsigned char* mask_raw = (const unsigned char*)d_in[2];
    const float* Wq  = (const float*)d_in[3];
    const float* bq  = (const float*)d_in[4];
    const float* Wk  = (const float*)d_in[5];
    const float* bk  = (const float*)d_in[6];
    const float* Wv  = (const float*)d_in[7];
    const float* bv  = (const float*)d_in[8];
    const float* Weq = (const float*)d_in[9];
    const float* beq = (const float*)d_in[10];
    const float* Wek = (const float*)d_in[11];
    const float* bek = (const float*)d_in[12];
    const float* Wev = (const float*)d_in[13];
    const float* bev = (const float*)d_in[14];
    const float* Wo  = (const float*)d_in[15];
    const float* bo  = (const float*)d_in[16];
    const float* Weo = (const float*)d_in[17];
    const float* beo = (const float*)d_in[18];
    float* out = (float*)d_out;

    float *qp, *kp, *vp, *op;
    cudaGetSymbolAddress((void**)&qp, g_q);
    cudaGetSymbolAddress((void**)&kp, g_k);
    cudaGetSymbolAddress((void**)&vp, g_v);
    cudaGetSymbolAddress((void**)&op, g_o);

    decode_mask_kernel<<<1, 256>>>(mask_raw);

    // Node projections: M=2048, K=128, N=512 -> qkv layout
    gemm_kernel<<<dim3(8, 32), 256>>>(nodes, Wq, bq, qp, 2048, 128, 512, 1024, 1024, 0, 0, 0);
    gemm_kernel<<<dim3(8, 32), 256>>>(nodes, Wk, bk, kp, 2048, 128, 512, 1024, 1024, 0, 0, 0);
    gemm_kernel<<<dim3(8, 32), 256>>>(nodes, Wv, bv, vp, 2048, 128, 512, 1024, 1024, 0, 0, 0);

    // Edge projections: M=4096, K=256, N=512 -> qkv layout, seq offset N
    gemm_kernel<<<dim3(8, 64), 256>>>(edges, Weq, beq, qp, 4096, 256, 512, 2048, 2048, 0, 0, 1024);
    gemm_kernel<<<dim3(8, 64), 256>>>(edges, Wek, bek, kp, 4096, 256, 512, 2048, 2048, 0, 0, 1024);
    gemm_kernel<<<dim3(8, 64), 256>>>(edges, Wev, bev, vp, 4096, 256, 512, 2048, 2048, 0, 0, 1024);

    // Flash attention
    static const int attn_smem = 3 * 64 * 65 * (int)sizeof(float);  // 49920 B
    cudaFuncSetAttribute(attn_kernel, cudaFuncAttributeMaxDynamicSharedMemorySize, attn_smem);
    attn_kernel<<<dim3(LTOT / 64, BSZ * HEADS), 256, attn_smem>>>();

    // Output projections
    // node_out: rows O[b, 0:1024, :], W [512,128] -> out[0 : 2*1024*128]
    gemm_kernel<<<dim3(2, 32), 256>>>(op, Wo, bo, out, 2048, 512, 128, 1024, 3072, 0, 1, 0);
    // edge_out: rows O[b, 1024:3072, :], W [512,256] -> out[2*1024*128 : ]
    gemm_kernel<<<dim3(4, 64), 256>>>(op, Weo, beo, out + 2 * 1024 * 128, 4096, 512, 256, 2048, 3072, 1024, 1, 0);
}

// round 2
// speedup vs baseline: 2.9663x; 2.9663x over previous
#include <cuda_runtime.h>
#include <float.h>
#include <math.h>
#include <stdint.h>

// Problem constants
#define BSZ   2
#define NN    1024
#define EE    2048
#define LTOT  3072          // NN + EE
#define HEADS 8
#define DHEAD 64
#define INNER 512           // HEADS*DHEAD
#define SCALE 0.125f        // DHEAD^-0.5

// Scratch (static device arrays; allocation is forbidden)
__device__ float g_q[BSZ * HEADS * LTOT * DHEAD];
__device__ float g_k[BSZ * HEADS * LTOT * DHEAD];
__device__ float g_v[BSZ * HEADS * LTOT * DHEAD];
__device__ float g_o[BSZ * LTOT * INNER];
__device__ int   g_mask[BSZ * LTOT];

// ---------------------------------------------------------------------------
// Helpers: tf32 convert + mma.sync m16n8k8 tf32
// ---------------------------------------------------------------------------
__device__ __forceinline__ uint32_t f2tf(float x) {
    uint32_t r;
    asm("cvt.rna.tf32.f32 %0, %1;" : "=r"(r) : "f"(x));
    return r;
}
__device__ __forceinline__ float tfbits(float x) {
    return __uint_as_float(f2tf(x));
}
__device__ __forceinline__ void mma_tf32(float c[4],
                                         uint32_t a0, uint32_t a1, uint32_t a2, uint32_t a3,
                                         uint32_t b0, uint32_t b1) {
    asm volatile(
        "mma.sync.aligned.m16n8k8.row.col.f32.tf32.tf32.f32 "
        "{%0,%1,%2,%3}, {%4,%5,%6,%7}, {%8,%9}, {%0,%1,%2,%3};"
        : "+f"(c[0]), "+f"(c[1]), "+f"(c[2]), "+f"(c[3])
        : "r"(a0), "r"(a1), "r"(a2), "r"(a3), "r"(b0), "r"(b1));
}

// ---------------------------------------------------------------------------
// Mask decode (bool width unknown: 1-byte vs 4-byte; deterministic heuristic)
// ---------------------------------------------------------------------------
__global__ void decode_mask_kernel(const unsigned char* __restrict__ raw) {
    __shared__ int partial[256];
    const int n = BSZ * LTOT;
    int tid = threadIdx.x;
    int cnt = 0;
    for (int i = tid; i < n; i += 256) cnt += (raw[i] != 0);
    partial[tid] = cnt;
    __syncthreads();
    for (int s = 128; s > 0; s >>= 1) {
        if (tid < s) partial[tid] += partial[tid + s];
        __syncthreads();
    }
    int width1 = partial[0] > (n * 3 / 8);
    const int* raw32 = (const int*)raw;
    for (int i = tid; i < n; i += 256)
        g_mask[i] = width1 ? (raw[i] != 0) : (raw32[i] != 0);
}

// ---------------------------------------------------------------------------
// tf32 tensor-core GEMM: C[M,Ncols] = A' @ W + bias.
// Block tile 64x64, BK=16, 128 threads = 4 warps in 2x2 grid, warp tile 32x32
// (2 m16-tiles x 4 n8-tiles). Source-row remap + two dst modes (same contract
// as round-1 gemm).
//   sA stride 20  (≡4 mod 32)  -> A-frag LDS conflict-free (banks 20g+c)
//   sW stride 72  (≡8 mod 32)  -> B-frag LDS conflict-free (banks 8q+g)
// ---------------------------------------------------------------------------
__global__ __launch_bounds__(128) void gemm_tf32_kernel(
        const float* __restrict__ A, const float* __restrict__ W,
        const float* __restrict__ bias, float* __restrict__ dst,
        int M, int K, int Ncols,
        int rowsPerBatch, int aBatchStride, int aSeqOff,
        int dstMode, int dstSeqOff) {
    __shared__ float sA[64 * 20];
    __shared__ float sW[16 * 72];

    const int tid = threadIdx.x;
    const int warp = tid >> 5, lane = tid & 31;
    const int g = lane >> 2, qd = lane & 3;
    const int wy = warp >> 1, wx = warp & 1;
    const int row0 = blockIdx.y * 64;
    const int col0 = blockIdx.x * 64;

    float acc[2][4][4] = {};

    for (int kt = 0; kt < K; kt += 16) {
        // Load A tile (row-remapped), convert to tf32
        #pragma unroll
        for (int t = 0; t < 8; t++) {
            int idx = tid + t * 128;          // 0..1023 over 64x16
            int i = idx >> 4, kk = idx & 15;
            int m = row0 + i;
            int bb = m / rowsPerBatch;
            int r = m - bb * rowsPerBatch;
            sA[i * 20 + kk] =
                tfbits(A[(size_t)(bb * aBatchStride + aSeqOff + r) * K + kt + kk]);
        }
        // Load W tile, convert to tf32
        #pragma unroll
        for (int t = 0; t < 8; t++) {
            int idx = tid + t * 128;          // 0..1023 over 16x64
            int kk = idx >> 6, j = idx & 63;
            sW[kk * 72 + j] = tfbits(W[(size_t)(kt + kk) * Ncols + col0 + j]);
        }
        __syncthreads();

        #pragma unroll
        for (int k8 = 0; k8 < 16; k8 += 8) {
            uint32_t a[2][4];
            #pragma unroll
            for (int t = 0; t < 2; t++) {
                int r = wy * 32 + t * 16 + g;
                a[t][0] = __float_as_uint(sA[r * 20 + k8 + qd]);
                a[t][1] = __float_as_uint(sA[(r + 8) * 20 + k8 + qd]);
                a[t][2] = __float_as_uint(sA[r * 20 + k8 + qd + 4]);
                a[t][3] = __float_as_uint(sA[(r + 8) * 20 + k8 + qd + 4]);
            }
            #pragma unroll
            for (int n = 0; n < 4; n++) {
                int cb = wx * 32 + n * 8 + g;
                uint32_t b0 = __float_as_uint(sW[(k8 + qd) * 72 + cb]);
                uint32_t b1 = __float_as_uint(sW[(k8 + qd + 4) * 72 + cb]);
                mma_tf32(acc[0][n], a[0][0], a[0][1], a[0][2], a[0][3], b0, b1);
                mma_tf32(acc[1][n], a[1][0], a[1][1], a[1][2], a[1][3], b0, b1);
            }
        }
        __syncthreads();
    }

    // Epilogue: bias + scatter
    #pragma unroll
    for (int t = 0; t < 2; t++) {
        #pragma unroll
        for (int hh = 0; hh < 2; hh++) {
            int m = row0 + wy * 32 + t * 16 + g + 8 * hh;
            int bb = m / rowsPerBatch;
            int r = m - bb * rowsPerBatch;
            #pragma unroll
            for (int n = 0; n < 4; n++) {
                int c = col0 + wx * 32 + n * 8 + 2 * qd;
                float v0 = acc[t][n][hh * 2 + 0] + bias[c];
                float v1 = acc[t][n][hh * 2 + 1] + bias[c + 1];
                if (dstMode == 0) {
                    int hidx = c >> 6, d = c & 63;
                    *(float2*)&dst[((size_t)(bb * HEADS + hidx) * LTOT +
                                    dstSeqOff + r) * DHEAD + d] = make_float2(v0, v1);
                } else {
                    *(float2*)&dst[(size_t)m * Ncols + c] = make_float2(v0, v1);
                }
            }
        }
    }
}

// ---------------------------------------------------------------------------
// Flash attention with tf32 tensor cores.
// Br=128 query rows / block, Bc=64 keys / tile, 4 warps (128 thr),
// each warp owns 32 query rows (2 m16-tiles), full 64-key width (8 n8-tiles).
// Online softmax stats in registers (quad shfl reductions). P staged through
// smem (C-frag layout != A-frag layout). All smem tf32-pre-converted.
// Strides: Qs/Ps/Ks = 68 (≡4 mod 32), Vs = 72 (≡8 mod 32) -> conflict-free.
// Fully-masked rows: all s=-FLT_MAX -> m=-FLT_MAX -> exp(0)=1 -> uniform,
// matching the reference.
// ---------------------------------------------------------------------------
#define QS_STR 68
#define PS_STR 68
#define KS_STR 68
#define VS_STR 72
#define ATTN_SMEM_FLOATS (128*QS_STR + 128*PS_STR + 64*KS_STR + 64*VS_STR)

__global__ __launch_bounds__(128) void attn_mma_kernel() {
    extern __shared__ float smx[];
    float* Qs = smx;                         // [128][68]
    float* Ps = Qs + 128 * QS_STR;           // [128][68]
    float* Ks = Ps + 128 * PS_STR;           // [64][68]
    float* Vs = Ks + 64 * KS_STR;            // [64][72]
    __shared__ int qm_s[128];
    __shared__ int km_s[64];

    const int tid = threadIdx.x;
    const int warp = tid >> 5, lane = tid & 31;
    const int g = lane >> 2, qd = lane & 3;
    const int bh = blockIdx.y, b = bh >> 3, h = bh & 7;
    const int q0 = blockIdx.x * 128;

    const float* Qg = g_q + (size_t)bh * LTOT * DHEAD;
    const float* Kg = g_k + (size_t)bh * LTOT * DHEAD;
    const float* Vg = g_v + (size_t)bh * LTOT * DHEAD;

    // Load Q tile once: scale, convert to tf32
    #pragma unroll
    for (int t = 0; t < 16; t++) {
        int idx = tid + t * 128;             // 0..2047 over 128 rows x 16 float4
        int i = idx >> 4, c4 = (idx & 15) * 4;
        float4 v = *(const float4*)&Qg[(size_t)(q0 + i) * DHEAD + c4];
        float* d = &Qs[i * QS_STR + c4];
        d[0] = tfbits(v.x * SCALE);
        d[1] = tfbits(v.y * SCALE);
        d[2] = tfbits(v.z * SCALE);
        d[3] = tfbits(v.w * SCALE);
    }
    qm_s[tid] = g_mask[b * LTOT + q0 + tid];
    __syncthreads();

    int qm_i[2][2];
    #pragma unroll
    for (int t = 0; t < 2; t++)
        #pragma unroll
        for (int hh = 0; hh < 2; hh++)
            qm_i[t][hh] = qm_s[warp * 32 + t * 16 + g + 8 * hh];

    float m_i[2][2], l_i[2][2];
    #pragma unroll
    for (int t = 0; t < 2; t++)
        #pragma unroll
        for (int hh = 0; hh < 2; hh++) { m_i[t][hh] = -FLT_MAX; l_i[t][hh] = 0.f; }

    float o[2][8][4] = {};

    for (int k0 = 0; k0 < LTOT; k0 += 64) {
        // Load K, V tiles (tf32)
        #pragma unroll
        for (int t = 0; t < 8; t++) {
            int idx = tid + t * 128;         // 0..1023 over 64 rows x 16 float4
            int i = idx >> 4, c4 = (idx & 15) * 4;
            float4 kv = *(const float4*)&Kg[(size_t)(k0 + i) * DHEAD + c4];
            float* kd = &Ks[i * KS_STR + c4];
            kd[0] = tfbits(kv.x); kd[1] = tfbits(kv.y);
            kd[2] = tfbits(kv.z); kd[3] = tfbits(kv.w);
            float4 vv = *(const float4*)&Vg[(size_t)(k0 + i) * DHEAD + c4];
            float* vd = &Vs[i * VS_STR + c4];
            vd[0] = tfbits(vv.x); vd[1] = tfbits(vv.y);
            vd[2] = tfbits(vv.z); vd[3] = tfbits(vv.w);
        }
        if (tid < 64) km_s[tid] = g_mask[b * LTOT + k0 + tid];
        __syncthreads();

        // ---- S = Q @ K^T (Q pre-scaled) ----
        float s[2][8][4] = {};
        #pragma unroll
        for (int kk = 0; kk < 8; kk++) {
            int d0 = kk * 8;
            uint32_t a[2][4];
            #pragma unroll
            for (int t = 0; t < 2; t++) {
                int r = warp * 32 + t * 16 + g;
                a[t][0] = __float_as_uint(Qs[r * QS_STR + d0 + qd]);
                a[t][1] = __float_as_uint(Qs[(r + 8) * QS_STR + d0 + qd]);
                a[t][2] = __float_as_uint(Qs[r * QS_STR + d0 + qd + 4]);
                a[t][3] = __float_as_uint(Qs[(r + 8) * QS_STR + d0 + qd + 4]);
            }
            #pragma unroll
            for (int nt = 0; nt < 8; nt++) {
                uint32_t b0 = __float_as_uint(Ks[(nt * 8 + g) * KS_STR + d0 + qd]);
                uint32_t b1 = __float_as_uint(Ks[(nt * 8 + g) * KS_STR + d0 + qd + 4]);
                mma_tf32(s[0][nt], a[0][0], a[0][1], a[0][2], a[0][3], b0, b1);
                mma_tf32(s[1][nt], a[1][0], a[1][1], a[1][2], a[1][3], b0, b1);
            }
        }

        // ---- mask ----
        int km2[8][2];
        #pragma unroll
        for (int nt = 0; nt < 8; nt++) {
            km2[nt][0] = km_s[nt * 8 + 2 * qd];
            km2[nt][1] = km_s[nt * 8 + 2 * qd + 1];
        }
        #pragma unroll
        for (int t = 0; t < 2; t++)
            #pragma unroll
            for (int nt = 0; nt < 8; nt++)
                #pragma unroll
                for (int e = 0; e < 2; e++) {
                    if (!(qm_i[t][0] && km2[nt][e])) s[t][nt][e]     = -FLT_MAX;
                    if (!(qm_i[t][1] && km2[nt][e])) s[t][nt][2 + e] = -FLT_MAX;
                }

        // ---- online softmax (per owned row) ----
        #pragma unroll
        for (int t = 0; t < 2; t++) {
            #pragma unroll
            for (int hh = 0; hh < 2; hh++) {
                float mx = -FLT_MAX;
                #pragma unroll
                for (int nt = 0; nt < 8; nt++)
                    mx = fmaxf(mx, fmaxf(s[t][nt][hh * 2], s[t][nt][hh * 2 + 1]));
                mx = fmaxf(mx, __shfl_xor_sync(0xffffffffu, mx, 1));
                mx = fmaxf(mx, __shfl_xor_sync(0xffffffffu, mx, 2));
                float mnew = fmaxf(m_i[t][hh], mx);
                float corr = __expf(m_i[t][hh] - mnew);
                m_i[t][hh] = mnew;
                float rs = 0.f;
                #pragma unroll
                for (int nt = 0; nt < 8; nt++) {
                    float p0 = __expf(s[t][nt][hh * 2]     - mnew);
                    float p1 = __expf(s[t][nt][hh * 2 + 1] - mnew);
                    rs += p0 + p1;
                    s[t][nt][hh * 2]     = p0;
                    s[t][nt][hh * 2 + 1] = p1;
                }
                rs += __shfl_xor_sync(0xffffffffu, rs, 1);
                rs += __shfl_xor_sync(0xffffffffu, rs, 2);
                l_i[t][hh] = l_i[t][hh] * corr + rs;
                #pragma unroll
                for (int nt = 0; nt < 8; nt++) {
                    o[t][nt][hh * 2]     *= corr;
                    o[t][nt][hh * 2 + 1] *= corr;
                }
            }
        }

        // ---- stage P (tf32) to smem; warp-local rows only ----
        #pragma unroll
        for (int t = 0; t < 2; t++)
            #pragma unroll
            for (int hh = 0; hh < 2; hh++) {
                int r = warp * 32 + t * 16 + g + 8 * hh;
                #pragma unroll
                for (int nt = 0; nt < 8; nt++) {
                    float2 pv;
                    pv.x = tfbits(s[t][nt][hh * 2]);
                    pv.y = tfbits(s[t][nt][hh * 2 + 1]);
                    *(float2*)&Ps[r * PS_STR + nt * 8 + 2 * qd] = pv;
                }
            }
        __syncwarp();

        // ---- O += P @ V ----
        #pragma unroll
        for (int kk = 0; kk < 8; kk++) {
            int j0 = kk * 8;
            uint32_t a[2][4];
            #pragma unroll
            for (int t = 0; t < 2; t++) {
                int r = warp * 32 + t * 16 + g;
                a[t][0] = __float_as_uint(Ps[r * PS_STR + j0 + qd]);
                a[t][1] = __float_as_uint(Ps[(r + 8) * PS_STR + j0 + qd]);
                a[t][2] = __float_as_uint(Ps[r * PS_STR + j0 + qd + 4]);
                a[t][3] = __float_as_uint(Ps[(r + 8) * PS_STR + j0 + qd + 4]);
            }
            #pragma unroll
            for (int nt = 0; nt < 8; nt++) {
                int d0 = nt * 8;
                uint32_t b0 = __float_as_uint(Vs[(j0 + qd) * VS_STR + d0 + g]);
                uint32_t b1 = __float_as_uint(Vs[(j0 + qd + 4) * VS_STR + d0 + g]);
                mma_tf32(o[0][nt], a[0][0], a[0][1], a[0][2], a[0][3], b0, b1);
                mma_tf32(o[1][nt], a[1][0], a[1][1], a[1][2], a[1][3], b0, b1);
            }
        }
        __syncthreads();   // before next tile overwrites Ks/Vs
    }

    // ---- normalize + write O in [B, L, INNER] layout ----
    #pragma unroll
    for (int t = 0; t < 2; t++)
        #pragma unroll
        for (int hh = 0; hh < 2; hh++) {
            float inv = 1.f / l_i[t][hh];
            int r = q0 + warp * 32 + t * 16 + g + 8 * hh;
            float* dstp = &g_o[(size_t)(b * LTOT + r) * INNER + h * DHEAD];
            #pragma unroll
            for (int nt = 0; nt < 8; nt++) {
                *(float2*)&dstp[nt * 8 + 2 * qd] =
                    make_float2(o[t][nt][hh * 2] * inv, o[t][nt][hh * 2 + 1] * inv);
            }
        }
}

// ---------------------------------------------------------------------------
// kernel_launch
// ---------------------------------------------------------------------------
extern "C" void kernel_launch(void* const* d_in, const int* in_sizes, int n_in,
                              void* d_out, int out_size) {
    const float* nodes = (const float*)d_in[0];
    const float* edges = (const float*)d_in[1];
    const unsigned char* mask_raw = (const unsigned char*)d_in[2];
    const float* Wq  = (const float*)d_in[3];
    const float* bq  = (const float*)d_in[4];
    const float* Wk  = (const float*)d_in[5];
    const float* bk  = (const float*)d_in[6];
    const float* Wv  = (const float*)d_in[7];
    const float* bv  = (const float*)d_in[8];
    const float* Weq = (const float*)d_in[9];
    const float* beq = (const float*)d_in[10];
    const float* Wek = (const float*)d_in[11];
    const float* bek = (const float*)d_in[12];
    const float* Wev = (const float*)d_in[13];
    const float* bev = (const float*)d_in[14];
    const float* Wo  = (const float*)d_in[15];
    const float* bo  = (const float*)d_in[16];
    const float* Weo = (const float*)d_in[17];
    const float* beo = (const float*)d_in[18];
    float* out = (float*)d_out;

    float *qp, *kp, *vp, *op;
    cudaGetSymbolAddress((void**)&qp, g_q);
    cudaGetSymbolAddress((void**)&kp, g_k);
    cudaGetSymbolAddress((void**)&vp, g_v);
    cudaGetSymbolAddress((void**)&op, g_o);

    decode_mask_kernel<<<1, 256>>>(mask_raw);

    // Node projections: M=2048, K=128, N=512 -> qkv layout
    gemm_tf32_kernel<<<dim3(8, 32), 128>>>(nodes, Wq, bq, qp, 2048, 128, 512, 1024, 1024, 0, 0, 0);
    gemm_tf32_kernel<<<dim3(8, 32), 128>>>(nodes, Wk, bk, kp, 2048, 128, 512, 1024, 1024, 0, 0, 0);
    gemm_tf32_kernel<<<dim3(8, 32), 128>>>(nodes, Wv, bv, vp, 2048, 128, 512, 1024, 1024, 0, 0, 0);

    // Edge projections: M=4096, K=256, N=512 -> qkv layout, seq offset 1024
    gemm_tf32_kernel<<<dim3(8, 64), 128>>>(edges, Weq, beq, qp, 4096, 256, 512, 2048, 2048, 0, 0, 1024);
    gemm_tf32_kernel<<<dim3(8, 64), 128>>>(edges, Wek, bek, kp, 4096, 256, 512, 2048, 2048, 0, 0, 1024);
    gemm_tf32_kernel<<<dim3(8, 64), 128>>>(edges, Wev, bev, vp, 4096, 256, 512, 2048, 2048, 0, 0, 1024);

    // Flash attention (tf32 mma)
    static const int attn_smem = ATTN_SMEM_FLOATS * (int)sizeof(float);  // 105472 B
    cudaFuncSetAttribute(attn_mma_kernel, cudaFuncAttributeMaxDynamicSharedMemorySize, attn_smem);
    attn_mma_kernel<<<dim3(LTOT / 128, BSZ * HEADS), 128, attn_smem>>>();

    // Output projections
    gemm_tf32_kernel<<<dim3(2, 32), 128>>>(op, Wo, bo, out, 2048, 512, 128, 1024, 3072, 0, 1, 0);
    gemm_tf32_kernel<<<dim3(4, 64), 128>>>(op, Weo, beo, out + 2 * 1024 * 128, 4096, 512, 256, 2048, 3072, 1024, 1, 0);
}

// round 3
// speedup vs baseline: 5.1914x; 1.7501x over previous
#include <cuda_runtime.h>
#include <cuda_fp16.h>
#include <float.h>
#include <math.h>
#include <stdint.h>

// Problem constants
#define BSZ   2
#define NN    1024
#define EE    2048
#define LTOT  3072
#define HEADS 8
#define DHEAD 64
#define INNER 512
#define SCALE 0.125f

// Scratch
__device__ float g_q[BSZ * HEADS * LTOT * DHEAD];
__device__ float g_k[BSZ * HEADS * LTOT * DHEAD];
__device__ float g_v[BSZ * HEADS * LTOT * DHEAD];
__device__ float g_o[BSZ * LTOT * INNER];
__device__ int   g_mask[BSZ * LTOT];

// ---------------------------------------------------------------------------
// PTX helpers
// ---------------------------------------------------------------------------
__device__ __forceinline__ uint32_t sptr(const void* p) {
    return (uint32_t)__cvta_generic_to_shared(p);
}
__device__ __forceinline__ void ldsm_x4(uint32_t& r0, uint32_t& r1,
                                        uint32_t& r2, uint32_t& r3, uint32_t addr) {
    asm volatile("ldmatrix.sync.aligned.m8n8.x4.shared.b16 {%0,%1,%2,%3}, [%4];"
                 : "=r"(r0), "=r"(r1), "=r"(r2), "=r"(r3) : "r"(addr));
}
__device__ __forceinline__ void ldsm_x4_t(uint32_t& r0, uint32_t& r1,
                                          uint32_t& r2, uint32_t& r3, uint32_t addr) {
    asm volatile("ldmatrix.sync.aligned.m8n8.x4.trans.shared.b16 {%0,%1,%2,%3}, [%4];"
                 : "=r"(r0), "=r"(r1), "=r"(r2), "=r"(r3) : "r"(addr));
}
__device__ __forceinline__ void mma_f16(float c[4],
                                        uint32_t a0, uint32_t a1, uint32_t a2, uint32_t a3,
                                        uint32_t b0, uint32_t b1) {
    asm volatile(
        "mma.sync.aligned.m16n8k16.row.col.f32.f16.f16.f32 "
        "{%0,%1,%2,%3}, {%4,%5,%6,%7}, {%8,%9}, {%0,%1,%2,%3};"
        : "+f"(c[0]), "+f"(c[1]), "+f"(c[2]), "+f"(c[3])
        : "r"(a0), "r"(a1), "r"(a2), "r"(a3), "r"(b0), "r"(b1));
}

// ---------------------------------------------------------------------------
// Mask decode (bool width unknown: 1-byte vs 4-byte; deterministic heuristic)
// ---------------------------------------------------------------------------
__global__ void decode_mask_kernel(const unsigned char* __restrict__ raw) {
    __shared__ int partial[256];
    const int n = BSZ * LTOT;
    int tid = threadIdx.x;
    int cnt = 0;
    for (int i = tid; i < n; i += 256) cnt += (raw[i] != 0);
    partial[tid] = cnt;
    __syncthreads();
    for (int s = 128; s > 0; s >>= 1) {
        if (tid < s) partial[tid] += partial[tid + s];
        __syncthreads();
    }
    int width1 = partial[0] > (n * 3 / 8);
    const int* raw32 = (const int*)raw;
    for (int i = tid; i < n; i += 256)
        g_mask[i] = width1 ? (raw[i] != 0) : (raw32[i] != 0);
}

// ---------------------------------------------------------------------------
// fp16 tensor-core GEMM: C[M,Ncols] = A' @ W + bias.
// Block tile 128x64, BK=32, 256 threads = 8 warps (4x2), warp tile 32x32.
// blockIdx.z selects one of up to 3 (W, bias, dst) triples (QKV fusion).
// sA: 128 rows x 40 halfs (80B row stride)  -> ldmatrix conflict-free
// sW: 32 rows x 72 halfs (144B row stride)  -> ldmatrix.trans conflict-free
// ---------------------------------------------------------------------------
__global__ __launch_bounds__(256) void gemm_f16_kernel(
        const float* __restrict__ A,
        const float* W0, const float* W1, const float* W2,
        const float* b0p, const float* b1p, const float* b2p,
        float* d0p, float* d1p, float* d2p,
        int M, int K, int Ncols,
        int rowsPerBatch, int aBatchStride, int aSeqOff,
        int dstMode, int dstSeqOff) {
    __shared__ __align__(16) __half sA[128 * 40];
    __shared__ __align__(16) __half sW[32 * 72];

    const int z = blockIdx.z;
    const float* W    = (z == 0) ? W0 : (z == 1) ? W1 : W2;
    const float* bias = (z == 0) ? b0p : (z == 1) ? b1p : b2p;
    float* dst        = (z == 0) ? d0p : (z == 1) ? d1p : d2p;

    const int tid = threadIdx.x;
    const int warp = tid >> 5, lane = tid & 31;
    const int g = lane >> 2, qd = lane & 3;
    const int wy = warp >> 1, wx = warp & 1;
    const int row0 = blockIdx.y * 128;
    const int col0 = blockIdx.x * 64;

    const uint32_t uA = sptr(sA);
    const uint32_t uW = sptr(sW);
    const int offA = ((lane & 7) + ((lane >> 3) & 1) * 8) * 80 + (lane >> 4) * 16;
    const int offW = ((lane & 7) + ((lane >> 3) & 1) * 8) * 144 + (lane >> 4) * 16;

    float acc[2][4][4] = {};

    for (int kt = 0; kt < K; kt += 32) {
        // A tile 128x32 fp32 -> half2
        #pragma unroll
        for (int t = 0; t < 8; t++) {
            int idx = tid + t * 256;           // 128 rows x 16 half2
            int i = idx >> 4, k2 = idx & 15;
            int m = row0 + i;
            int bb = m / rowsPerBatch;
            int r = m - bb * rowsPerBatch;
            float2 v = *(const float2*)&A[(size_t)(bb * aBatchStride + aSeqOff + r) * K + kt + 2 * k2];
            ((__half2*)sA)[i * 20 + k2] = __floats2half2_rn(v.x, v.y);
        }
        // W tile 32x64 fp32 -> half2
        #pragma unroll
        for (int t = 0; t < 4; t++) {
            int idx = tid + t * 256;           // 32 rows x 32 half2
            int kr = idx >> 5, n2 = idx & 31;
            float2 v = *(const float2*)&W[(size_t)(kt + kr) * Ncols + col0 + 2 * n2];
            ((__half2*)sW)[kr * 36 + n2] = __floats2half2_rn(v.x, v.y);
        }
        __syncthreads();

        #pragma unroll
        for (int kk = 0; kk < 2; kk++) {
            uint32_t a[2][4];
            #pragma unroll
            for (int mt = 0; mt < 2; mt++)
                ldsm_x4(a[mt][0], a[mt][1], a[mt][2], a[mt][3],
                        uA + (wy * 32 + mt * 16) * 80 + kk * 32 + offA);
            #pragma unroll
            for (int p = 0; p < 2; p++) {
                uint32_t b0, b1, b2, b3;
                ldsm_x4_t(b0, b1, b2, b3,
                          uW + kk * 16 * 144 + (wx * 32 + p * 16) * 2 + offW);
                mma_f16(acc[0][2 * p],     a[0][0], a[0][1], a[0][2], a[0][3], b0, b1);
                mma_f16(acc[0][2 * p + 1], a[0][0], a[0][1], a[0][2], a[0][3], b2, b3);
                mma_f16(acc[1][2 * p],     a[1][0], a[1][1], a[1][2], a[1][3], b0, b1);
                mma_f16(acc[1][2 * p + 1], a[1][0], a[1][1], a[1][2], a[1][3], b2, b3);
            }
        }
        __syncthreads();
    }

    // Epilogue: bias + scatter
    #pragma unroll
    for (int mt = 0; mt < 2; mt++) {
        #pragma unroll
        for (int hh = 0; hh < 2; hh++) {
            int m = row0 + wy * 32 + mt * 16 + g + 8 * hh;
            int bb = m / rowsPerBatch;
            int r = m - bb * rowsPerBatch;
            #pragma unroll
            for (int n = 0; n < 4; n++) {
                int c = col0 + wx * 32 + n * 8 + 2 * qd;
                float v0 = acc[mt][n][hh * 2 + 0] + bias[c];
                float v1 = acc[mt][n][hh * 2 + 1] + bias[c + 1];
                if (dstMode == 0) {
                    int hidx = c >> 6, d = c & 63;
                    *(float2*)&dst[((size_t)(bb * HEADS + hidx) * LTOT +
                                    dstSeqOff + r) * DHEAD + d] = make_float2(v0, v1);
                } else {
                    *(float2*)&dst[(size_t)m * Ncols + c] = make_float2(v0, v1);
                }
            }
        }
    }
}

// ---------------------------------------------------------------------------
// Flash attention, fp16 mma + ldmatrix.
// Br=128, Bc=64, 256 threads = 8 warps; warp w owns rows w*16..w*16+15.
// Smem rows are 72 halfs (144B): ldmatrix phases conflict-free (144 ≡ 16 mod 128).
// V consumed via ldmatrix.x4.trans — no software transpose.
// Online softmax identical in semantics to the reference (-FLT_MAX masking;
// fully-masked rows -> uniform).
// ---------------------------------------------------------------------------
#define AT_ROW_H 72                           // halfs per smem row
#define ATTN_SMEM_BYTES ((128 + 128 + 64 + 64) * AT_ROW_H * 2)   // 55296

__global__ __launch_bounds__(256, 2) void attn_f16_kernel() {
    extern __shared__ __align__(16) char smraw[];
    __half* Qs = (__half*)smraw;              // [128][72]
    __half* Ps = Qs + 128 * AT_ROW_H;         // [128][72]
    __half* Ks = Ps + 128 * AT_ROW_H;         // [64][72]
    __half* Vs = Ks + 64 * AT_ROW_H;          // [64][72]
    __shared__ int qm_s[128];
    __shared__ int km_s[64];

    const int tid = threadIdx.x;
    const int warp = tid >> 5, lane = tid & 31;
    const int g = lane >> 2, qd = lane & 3;
    const int bh = blockIdx.y, b = bh >> 3, h = bh & 7;
    const int q0 = blockIdx.x * 128;

    const float* Qg = g_q + (size_t)bh * LTOT * DHEAD;
    const float* Kg = g_k + (size_t)bh * LTOT * DHEAD;
    const float* Vg = g_v + (size_t)bh * LTOT * DHEAD;

    const uint32_t uQ = sptr(Qs), uP = sptr(Ps), uK = sptr(Ks), uV = sptr(Vs);
    const int offA = ((lane & 7) + ((lane >> 3) & 1) * 8) * 144 + (lane >> 4) * 16;
    const int offK = ((lane & 7) + ((lane >> 4) & 1) * 8) * 144 + ((lane >> 3) & 1) * 16;

    // Load Q (scaled) -> fp16 smem
    #pragma unroll
    for (int t = 0; t < 8; t++) {
        int idx = tid + t * 256;              // 128 rows x 16 float4
        int i = idx >> 4, c4 = (idx & 15) * 4;
        float4 v = *(const float4*)&Qg[(size_t)(q0 + i) * DHEAD + c4];
        __half2* d = (__half2*)Qs + i * 36 + (c4 >> 1);
        d[0] = __floats2half2_rn(v.x * SCALE, v.y * SCALE);
        d[1] = __floats2half2_rn(v.z * SCALE, v.w * SCALE);
    }
    if (tid < 128) qm_s[tid] = g_mask[b * LTOT + q0 + tid];
    __syncthreads();

    int qm_i[2];
    qm_i[0] = qm_s[warp * 16 + g];
    qm_i[1] = qm_s[warp * 16 + g + 8];

    float m_i[2] = {-FLT_MAX, -FLT_MAX};
    float l_i[2] = {0.f, 0.f};
    float o[8][4] = {};

    for (int k0 = 0; k0 < LTOT; k0 += 64) {
        // Load K, V tiles -> fp16 smem
        #pragma unroll
        for (int t = 0; t < 4; t++) {
            int idx = tid + t * 256;          // 64 rows x 16 float4
            int i = idx >> 4, c4 = (idx & 15) * 4;
            float4 kv = *(const float4*)&Kg[(size_t)(k0 + i) * DHEAD + c4];
            __half2* kd = (__half2*)Ks + i * 36 + (c4 >> 1);
            kd[0] = __floats2half2_rn(kv.x, kv.y);
            kd[1] = __floats2half2_rn(kv.z, kv.w);
            float4 vv = *(const float4*)&Vg[(size_t)(k0 + i) * DHEAD + c4];
            __half2* vd = (__half2*)Vs + i * 36 + (c4 >> 1);
            vd[0] = __floats2half2_rn(vv.x, vv.y);
            vd[1] = __floats2half2_rn(vv.z, vv.w);
        }
        if (tid < 64) km_s[tid] = g_mask[b * LTOT + k0 + tid];
        __syncthreads();

        // ---- S = Q @ K^T ----
        float s[8][4] = {};
        #pragma unroll
        for (int kk = 0; kk < 4; kk++) {
            uint32_t a0, a1, a2, a3;
            ldsm_x4(a0, a1, a2, a3, uQ + (warp * 16) * 144 + kk * 32 + offA);
            #pragma unroll
            for (int p = 0; p < 4; p++) {
                uint32_t b0, b1, b2, b3;
                ldsm_x4(b0, b1, b2, b3, uK + p * 16 * 144 + kk * 32 + offK);
                mma_f16(s[2 * p],     a0, a1, a2, a3, b0, b1);
                mma_f16(s[2 * p + 1], a0, a1, a2, a3, b2, b3);
            }
        }

        // ---- mask ----
        #pragma unroll
        for (int nt = 0; nt < 8; nt++) {
            int k0m = km_s[nt * 8 + 2 * qd];
            int k1m = km_s[nt * 8 + 2 * qd + 1];
            if (!(qm_i[0] && k0m)) s[nt][0] = -FLT_MAX;
            if (!(qm_i[0] && k1m)) s[nt][1] = -FLT_MAX;
            if (!(qm_i[1] && k0m)) s[nt][2] = -FLT_MAX;
            if (!(qm_i[1] && k1m)) s[nt][3] = -FLT_MAX;
        }

        // ---- online softmax ----
        float corr[2];
        #pragma unroll
        for (int hh = 0; hh < 2; hh++) {
            float mx = -FLT_MAX;
            #pragma unroll
            for (int nt = 0; nt < 8; nt++)
                mx = fmaxf(mx, fmaxf(s[nt][hh * 2], s[nt][hh * 2 + 1]));
            mx = fmaxf(mx, __shfl_xor_sync(0xffffffffu, mx, 1));
            mx = fmaxf(mx, __shfl_xor_sync(0xffffffffu, mx, 2));
            float mnew = fmaxf(m_i[hh], mx);
            corr[hh] = __expf(m_i[hh] - mnew);
            m_i[hh] = mnew;
            float rs = 0.f;
            #pragma unroll
            for (int nt = 0; nt < 8; nt++) {
                float p0 = __expf(s[nt][hh * 2]     - mnew);
                float p1 = __expf(s[nt][hh * 2 + 1] - mnew);
                rs += p0 + p1;
                s[nt][hh * 2]     = p0;
                s[nt][hh * 2 + 1] = p1;
            }
            rs += __shfl_xor_sync(0xffffffffu, rs, 1);
            rs += __shfl_xor_sync(0xffffffffu, rs, 2);
            l_i[hh] = l_i[hh] * corr[hh] + rs;
            #pragma unroll
            for (int nt = 0; nt < 8; nt++) {
                o[nt][hh * 2]     *= corr[hh];
                o[nt][hh * 2 + 1] *= corr[hh];
            }
        }

        // ---- stage P (fp16) to smem; rows are warp-local ----
        #pragma unroll
        for (int hh = 0; hh < 2; hh++) {
            int r = warp * 16 + g + 8 * hh;
            #pragma unroll
            for (int nt = 0; nt < 8; nt++) {
                ((__half2*)Ps)[r * 36 + nt * 4 + qd] =
                    __floats2half2_rn(s[nt][hh * 2], s[nt][hh * 2 + 1]);
            }
        }
        __syncwarp();

        // ---- O += P @ V ----
        #pragma unroll
        for (int jj = 0; jj < 4; jj++) {
            uint32_t a0, a1, a2, a3;
            ldsm_x4(a0, a1, a2, a3, uP + (warp * 16) * 144 + jj * 32 + offA);
            #pragma unroll
            for (int p = 0; p < 4; p++) {
                uint32_t b0, b1, b2, b3;
                ldsm_x4_t(b0, b1, b2, b3, uV + jj * 16 * 144 + p * 32 + offA);
                mma_f16(o[2 * p],     a0, a1, a2, a3, b0, b1);
                mma_f16(o[2 * p + 1], a0, a1, a2, a3, b2, b3);
            }
        }
        __syncthreads();   // before next tile overwrites Ks/Vs
    }

    // ---- normalize + write O in [B, L, INNER] layout ----
    #pragma unroll
    for (int hh = 0; hh < 2; hh++) {
        float inv = 1.f / l_i[hh];
        int r = q0 + warp * 16 + g + 8 * hh;
        float* dstp = &g_o[(size_t)(b * LTOT + r) * INNER + h * DHEAD];
        #pragma unroll
        for (int nt = 0; nt < 8; nt++) {
            *(float2*)&dstp[nt * 8 + 2 * qd] =
                make_float2(o[nt][hh * 2] * inv, o[nt][hh * 2 + 1] * inv);
        }
    }
}

// ---------------------------------------------------------------------------
// kernel_launch
// ---------------------------------------------------------------------------
extern "C" void kernel_launch(void* const* d_in, const int* in_sizes, int n_in,
                              void* d_out, int out_size) {
    const float* nodes = (const float*)d_in[0];
    const float* edges = (const float*)d_in[1];
    const unsigned char* mask_raw = (const unsigned char*)d_in[2];
    const float* Wq  = (const float*)d_in[3];
    const float* bq  = (const float*)d_in[4];
    const float* Wk  = (const float*)d_in[5];
    const float* bk  = (const float*)d_in[6];
    const float* Wv  = (const float*)d_in[7];
    const float* bv  = (const float*)d_in[8];
    const float* Weq = (const float*)d_in[9];
    const float* beq = (const float*)d_in[10];
    const float* Wek = (const float*)d_in[11];
    const float* bek = (const float*)d_in[12];
    const float* Wev = (const float*)d_in[13];
    const float* bev = (const float*)d_in[14];
    const float* Wo  = (const float*)d_in[15];
    const float* bo  = (const float*)d_in[16];
    const float* Weo = (const float*)d_in[17];
    const float* beo = (const float*)d_in[18];
    float* out = (float*)d_out;

    float *qp, *kp, *vp, *op;
    cudaGetSymbolAddress((void**)&qp, g_q);
    cudaGetSymbolAddress((void**)&kp, g_k);
    cudaGetSymbolAddress((void**)&vp, g_v);
    cudaGetSymbolAddress((void**)&op, g_o);

    decode_mask_kernel<<<1, 256>>>(mask_raw);

    // Node Q/K/V projections fused (blockIdx.z): M=2048, K=128, N=512
    gemm_f16_kernel<<<dim3(8, 16, 3), 256>>>(
        nodes, Wq, Wk, Wv, bq, bk, bv, qp, kp, vp,
        2048, 128, 512, 1024, 1024, 0, 0, 0);

    // Edge Q/K/V projections fused: M=4096, K=256, N=512, seq offset 1024
    gemm_f16_kernel<<<dim3(8, 32, 3), 256>>>(
        edges, Weq, Wek, Wev, beq, bek, bev, qp, kp, vp,
        4096, 256, 512, 2048, 2048, 0, 0, 1024);

    // Flash attention
    cudaFuncSetAttribute(attn_f16_kernel,
                         cudaFuncAttributeMaxDynamicSharedMemorySize, ATTN_SMEM_BYTES);
    attn_f16_kernel<<<dim3(LTOT / 128, BSZ * HEADS), 256, ATTN_SMEM_BYTES>>>();

    // Output projections
    gemm_f16_kernel<<<dim3(2, 16, 1), 256>>>(
        op, Wo, Wo, Wo, bo, bo, bo, out, out, out,
        2048, 512, 128, 1024, 3072, 0, 1, 0);
    gemm_f16_kernel<<<dim3(4, 32, 1), 256>>>(
        op, Weo, Weo, Weo, beo, beo, beo,
        out + 2 * 1024 * 128, out + 2 * 1024 * 128, out + 2 * 1024 * 128,
        4096, 512, 256, 2048, 3072, 1024, 1, 0);
}

// round 4
// speedup vs baseline: 6.5091x; 1.2538x over previous
#include <cuda_runtime.h>
#include <cuda_fp16.h>
#include <float.h>
#include <math.h>
#include <stdint.h>

// Problem constants
#define BSZ   2
#define NN    1024
#define EE    2048
#define LTOT  3072
#define HEADS 8
#define DHEAD 64
#define INNER 512
#define SCALE 0.125f

// Scratch (fp16 intermediates)
__device__ __half g_qh[BSZ * HEADS * LTOT * DHEAD];   // pre-scaled by SCALE
__device__ __half g_kh[BSZ * HEADS * LTOT * DHEAD];
__device__ __half g_vh[BSZ * HEADS * LTOT * DHEAD];
__device__ __half g_oh[BSZ * LTOT * INNER];
__device__ int    g_mask[BSZ * LTOT];

// ---------------------------------------------------------------------------
// PTX helpers
// ---------------------------------------------------------------------------
__device__ __forceinline__ uint32_t sptr(const void* p) {
    return (uint32_t)__cvta_generic_to_shared(p);
}
__device__ __forceinline__ void ldsm_x4(uint32_t& r0, uint32_t& r1,
                                        uint32_t& r2, uint32_t& r3, uint32_t addr) {
    asm volatile("ldmatrix.sync.aligned.m8n8.x4.shared.b16 {%0,%1,%2,%3}, [%4];"
                 : "=r"(r0), "=r"(r1), "=r"(r2), "=r"(r3) : "r"(addr));
}
__device__ __forceinline__ void ldsm_x4_t(uint32_t& r0, uint32_t& r1,
                                          uint32_t& r2, uint32_t& r3, uint32_t addr) {
    asm volatile("ldmatrix.sync.aligned.m8n8.x4.trans.shared.b16 {%0,%1,%2,%3}, [%4];"
                 : "=r"(r0), "=r"(r1), "=r"(r2), "=r"(r3) : "r"(addr));
}
__device__ __forceinline__ void mma_f16(float c[4],
                                        uint32_t a0, uint32_t a1, uint32_t a2, uint32_t a3,
                                        uint32_t b0, uint32_t b1) {
    asm volatile(
        "mma.sync.aligned.m16n8k16.row.col.f32.f16.f16.f32 "
        "{%0,%1,%2,%3}, {%4,%5,%6,%7}, {%8,%9}, {%0,%1,%2,%3};"
        : "+f"(c[0]), "+f"(c[1]), "+f"(c[2]), "+f"(c[3])
        : "r"(a0), "r"(a1), "r"(a2), "r"(a3), "r"(b0), "r"(b1));
}
__device__ __forceinline__ void cp16(uint32_t dst, const void* src) {
    asm volatile("cp.async.cg.shared.global [%0], [%1], 16;" :: "r"(dst), "l"(src));
}
__device__ __forceinline__ void cp_commit() {
    asm volatile("cp.async.commit_group;");
}
__device__ __forceinline__ void cp_wait0() {
    asm volatile("cp.async.wait_group 0;");
}
__device__ __forceinline__ uint32_t packh2(float x, float y) {
    __half2 h = __floats2half2_rn(x, y);
    return *reinterpret_cast<uint32_t*>(&h);
}

// ---------------------------------------------------------------------------
// Mask decode (bool width unknown: 1-byte vs 4-byte; deterministic heuristic)
// ---------------------------------------------------------------------------
__global__ void decode_mask_kernel(const unsigned char* __restrict__ raw) {
    __shared__ int partial[256];
    const int n = BSZ * LTOT;
    int tid = threadIdx.x;
    int cnt = 0;
    for (int i = tid; i < n; i += 256) cnt += (raw[i] != 0);
    partial[tid] = cnt;
    __syncthreads();
    for (int s = 128; s > 0; s >>= 1) {
        if (tid < s) partial[tid] += partial[tid + s];
        __syncthreads();
    }
    int width1 = partial[0] > (n * 3 / 8);
    const int* raw32 = (const int*)raw;
    for (int i = tid; i < n; i += 256)
        g_mask[i] = width1 ? (raw[i] != 0) : (raw32[i] != 0);
}

// ---------------------------------------------------------------------------
// fp16 tensor-core GEMM: C = A' @ W + bias (then * scale).
// Block tile 128x64, BK=32, 256 threads = 8 warps (4x2), warp tile 32x32.
// blockIdx.z selects (W, bias, dst, scale) triple.
// AHALF: A is fp16 (attention output); else fp32.
// dstMode 0: scatter fp16 into [B,H,L,D]; dstMode 1: fp32 [m, Ncols].
// ---------------------------------------------------------------------------
template <bool AHALF>
__global__ __launch_bounds__(256) void gemm_f16_kernel(
        const void* __restrict__ Ap,
        const float* W0, const float* W1, const float* W2,
        const float* b0p, const float* b1p, const float* b2p,
        void* d0p, void* d1p, void* d2p,
        float s0, float s1, float s2,
        int M, int K, int Ncols,
        int rowsPerBatch, int aBatchStride, int aSeqOff,
        int dstMode, int dstSeqOff) {
    __shared__ __align__(16) __half sA[128 * 40];
    __shared__ __align__(16) __half sW[32 * 72];

    const int z = blockIdx.z;
    const float* W    = (z == 0) ? W0 : (z == 1) ? W1 : W2;
    const float* bias = (z == 0) ? b0p : (z == 1) ? b1p : b2p;
    void* dst         = (z == 0) ? d0p : (z == 1) ? d1p : d2p;
    const float scl   = (z == 0) ? s0 : (z == 1) ? s1 : s2;

    const int tid = threadIdx.x;
    const int warp = tid >> 5, lane = tid & 31;
    const int g = lane >> 2, qd = lane & 3;
    const int wy = warp >> 1, wx = warp & 1;
    const int row0 = blockIdx.y * 128;
    const int col0 = blockIdx.x * 64;

    const uint32_t uA = sptr(sA);
    const uint32_t uW = sptr(sW);
    const int offA = ((lane & 7) + ((lane >> 3) & 1) * 8) * 80 + (lane >> 4) * 16;
    const int offW = ((lane & 7) + ((lane >> 3) & 1) * 8) * 144 + (lane >> 4) * 16;

    float acc[2][4][4] = {};

    for (int kt = 0; kt < K; kt += 32) {
        #pragma unroll
        for (int t = 0; t < 8; t++) {
            int idx = tid + t * 256;           // 128 rows x 16 half2
            int i = idx >> 4, k2 = idx & 15;
            int m = row0 + i;
            int bb = m / rowsPerBatch;
            int r = m - bb * rowsPerBatch;
            size_t arow = (size_t)(bb * aBatchStride + aSeqOff + r) * K + kt + 2 * k2;
            if (AHALF) {
                ((__half2*)sA)[i * 20 + k2] = *(const __half2*)((const __half*)Ap + arow);
            } else {
                float2 v = *(const float2*)((const float*)Ap + arow);
                ((__half2*)sA)[i * 20 + k2] = __floats2half2_rn(v.x, v.y);
            }
        }
        #pragma unroll
        for (int t = 0; t < 4; t++) {
            int idx = tid + t * 256;           // 32 rows x 32 half2
            int kr = idx >> 5, n2 = idx & 31;
            float2 v = *(const float2*)&W[(size_t)(kt + kr) * Ncols + col0 + 2 * n2];
            ((__half2*)sW)[kr * 36 + n2] = __floats2half2_rn(v.x, v.y);
        }
        __syncthreads();

        #pragma unroll
        for (int kk = 0; kk < 2; kk++) {
            uint32_t a[2][4];
            #pragma unroll
            for (int mt = 0; mt < 2; mt++)
                ldsm_x4(a[mt][0], a[mt][1], a[mt][2], a[mt][3],
                        uA + (wy * 32 + mt * 16) * 80 + kk * 32 + offA);
            #pragma unroll
            for (int p = 0; p < 2; p++) {
                uint32_t b0, b1, b2, b3;
                ldsm_x4_t(b0, b1, b2, b3,
                          uW + kk * 16 * 144 + (wx * 32 + p * 16) * 2 + offW);
                mma_f16(acc[0][2 * p],     a[0][0], a[0][1], a[0][2], a[0][3], b0, b1);
                mma_f16(acc[0][2 * p + 1], a[0][0], a[0][1], a[0][2], a[0][3], b2, b3);
                mma_f16(acc[1][2 * p],     a[1][0], a[1][1], a[1][2], a[1][3], b0, b1);
                mma_f16(acc[1][2 * p + 1], a[1][0], a[1][1], a[1][2], a[1][3], b2, b3);
            }
        }
        __syncthreads();
    }

    #pragma unroll
    for (int mt = 0; mt < 2; mt++) {
        #pragma unroll
        for (int hh = 0; hh < 2; hh++) {
            int m = row0 + wy * 32 + mt * 16 + g + 8 * hh;
            int bb = m / rowsPerBatch;
            int r = m - bb * rowsPerBatch;
            #pragma unroll
            for (int n = 0; n < 4; n++) {
                int c = col0 + wx * 32 + n * 8 + 2 * qd;
                float v0 = (acc[mt][n][hh * 2 + 0] + bias[c]) * scl;
                float v1 = (acc[mt][n][hh * 2 + 1] + bias[c + 1]) * scl;
                if (dstMode == 0) {
                    int hidx = c >> 6, d = c & 63;
                    __half* dh = (__half*)dst;
                    *(__half2*)&dh[((size_t)(bb * HEADS + hidx) * LTOT +
                                    dstSeqOff + r) * DHEAD + d] = __floats2half2_rn(v0, v1);
                } else {
                    float* df = (float*)dst;
                    *(float2*)&df[(size_t)m * Ncols + c] = make_float2(v0, v1);
                }
            }
        }
    }
}

// ---------------------------------------------------------------------------
// Flash attention: fp16 mma, Q fragments register-resident, P kept in
// registers (C-frag == A-frag layout), K/V cp.async double-buffered.
// Br=128, Bc=64, 256 threads = 8 warps; warp w owns rows w*16..w*16+15.
// Smem rows 72 halfs (144B): ldmatrix phases conflict-free.
// ---------------------------------------------------------------------------
#define KVSTR 72
#define KVBUF_H (64 * KVSTR)                    // halfs per buffer
#define KVBUF_B (KVBUF_H * 2)                   // bytes
#define ATTN_SMEM_BYTES (4 * KVBUF_B + LTOT)    // 2xK + 2xV + mask bytes

__global__ __launch_bounds__(256, 2) void attn_f16_kernel() {
    extern __shared__ __align__(16) char smraw[];
    __half* Kh = (__half*)smraw;                 // [2][64][72]
    __half* Vh = (__half*)(smraw + 2 * KVBUF_B); // [2][64][72]
    char* mk = smraw + 4 * KVBUF_B;              // [3072]

    const int tid = threadIdx.x;
    const int warp = tid >> 5, lane = tid & 31;
    const int g = lane >> 2, qd = lane & 3;
    const int bh = blockIdx.y, b = bh >> 3, h = bh & 7;
    const int q0 = blockIdx.x * 128;

    const __half* Qg = g_qh + (size_t)bh * LTOT * DHEAD;
    const __half* Kg = g_kh + (size_t)bh * LTOT * DHEAD;
    const __half* Vg = g_vh + (size_t)bh * LTOT * DHEAD;

    const uint32_t uK = sptr(Kh), uV = sptr(Vh);
    const int offA = ((lane & 7) + ((lane >> 3) & 1) * 8) * 144 + (lane >> 4) * 16;
    const int offK = ((lane & 7) + ((lane >> 4) & 1) * 8) * 144 + ((lane >> 3) & 1) * 16;

    // Prologue: start loading tile 0 (K and V), 16B per thread x2
    {
        int row = tid >> 3, ch = (tid & 7) * 16;           // rows 0..31
        cp16(uK + row * 144 + ch, Kg + (size_t)row * 64 + (ch >> 1));
        cp16(uV + row * 144 + ch, Vg + (size_t)row * 64 + (ch >> 1));
        int row2 = row + 32;
        cp16(uK + row2 * 144 + ch, Kg + (size_t)row2 * 64 + (ch >> 1));
        cp16(uV + row2 * 144 + ch, Vg + (size_t)row2 * 64 + (ch >> 1));
        cp_commit();
    }

    // Mask -> smem bytes
    for (int i = tid; i < LTOT; i += 256) mk[i] = (char)g_mask[b * LTOT + i];

    // Q fragments, register-resident (loop-invariant). Pre-scaled in gmem.
    uint32_t qa[4][4];
    {
        const __half* qr0 = Qg + (size_t)(q0 + warp * 16 + g) * DHEAD;
        const __half* qr1 = qr0 + 8 * DHEAD;
        #pragma unroll
        for (int kk = 0; kk < 4; kk++) {
            int c = kk * 16 + 2 * qd;
            qa[kk][0] = *(const uint32_t*)(qr0 + c);
            qa[kk][1] = *(const uint32_t*)(qr1 + c);
            qa[kk][2] = *(const uint32_t*)(qr0 + c + 8);
            qa[kk][3] = *(const uint32_t*)(qr1 + c + 8);
        }
    }
    __syncthreads();   // mask visible

    int qm_i[2];
    qm_i[0] = mk[q0 + warp * 16 + g];
    qm_i[1] = mk[q0 + warp * 16 + g + 8];

    float m_i[2] = {-FLT_MAX, -FLT_MAX};
    float l_i[2] = {0.f, 0.f};
    float o[8][4] = {};

    const int NIT = LTOT / 64;
    for (int it = 0; it < NIT; it++) {
        const int bf = it & 1;
        const int k0 = it * 64;
        cp_wait0();
        __syncthreads();   // tile `it` visible to all; all warps done with buf bf^1

        // Issue loads for tile it+1 into the other buffer
        if (it + 1 < NIT) {
            uint32_t uKn = uK + (bf ^ 1) * KVBUF_B;
            uint32_t uVn = uV + (bf ^ 1) * KVBUF_B;
            int gk = (it + 1) * 64;
            int row = tid >> 3, ch = (tid & 7) * 16;
            cp16(uKn + row * 144 + ch, Kg + (size_t)(gk + row) * 64 + (ch >> 1));
            cp16(uVn + row * 144 + ch, Vg + (size_t)(gk + row) * 64 + (ch >> 1));
            int row2 = row + 32;
            cp16(uKn + row2 * 144 + ch, Kg + (size_t)(gk + row2) * 64 + (ch >> 1));
            cp16(uVn + row2 * 144 + ch, Vg + (size_t)(gk + row2) * 64 + (ch >> 1));
            cp_commit();
        }

        const uint32_t uKb = uK + bf * KVBUF_B;
        const uint32_t uVb = uV + bf * KVBUF_B;

        // ---- S = Q @ K^T ----
        float s[8][4] = {};
        #pragma unroll
        for (int kk = 0; kk < 4; kk++) {
            #pragma unroll
            for (int p = 0; p < 4; p++) {
                uint32_t b0, b1, b2, b3;
                ldsm_x4(b0, b1, b2, b3, uKb + p * 16 * 144 + kk * 32 + offK);
                mma_f16(s[2 * p],     qa[kk][0], qa[kk][1], qa[kk][2], qa[kk][3], b0, b1);
                mma_f16(s[2 * p + 1], qa[kk][0], qa[kk][1], qa[kk][2], qa[kk][3], b2, b3);
            }
        }

        // ---- mask ----
        #pragma unroll
        for (int nt = 0; nt < 8; nt++) {
            int k0m = mk[k0 + nt * 8 + 2 * qd];
            int k1m = mk[k0 + nt * 8 + 2 * qd + 1];
            if (!(qm_i[0] && k0m)) s[nt][0] = -FLT_MAX;
            if (!(qm_i[0] && k1m)) s[nt][1] = -FLT_MAX;
            if (!(qm_i[1] && k0m)) s[nt][2] = -FLT_MAX;
            if (!(qm_i[1] && k1m)) s[nt][3] = -FLT_MAX;
        }

        // ---- online softmax ----
        #pragma unroll
        for (int hh = 0; hh < 2; hh++) {
            float mx = -FLT_MAX;
            #pragma unroll
            for (int nt = 0; nt < 8; nt++)
                mx = fmaxf(mx, fmaxf(s[nt][hh * 2], s[nt][hh * 2 + 1]));
            mx = fmaxf(mx, __shfl_xor_sync(0xffffffffu, mx, 1));
            mx = fmaxf(mx, __shfl_xor_sync(0xffffffffu, mx, 2));
            float mnew = fmaxf(m_i[hh], mx);
            float corr = __expf(m_i[hh] - mnew);
            m_i[hh] = mnew;
            float rs = 0.f;
            #pragma unroll
            for (int nt = 0; nt < 8; nt++) {
                float p0 = __expf(s[nt][hh * 2]     - mnew);
                float p1 = __expf(s[nt][hh * 2 + 1] - mnew);
                rs += p0 + p1;
                s[nt][hh * 2]     = p0;
                s[nt][hh * 2 + 1] = p1;
            }
            rs += __shfl_xor_sync(0xffffffffu, rs, 1);
            rs += __shfl_xor_sync(0xffffffffu, rs, 2);
            l_i[hh] = l_i[hh] * corr + rs;
            #pragma unroll
            for (int nt = 0; nt < 8; nt++) {
                o[nt][hh * 2]     *= corr;
                o[nt][hh * 2 + 1] *= corr;
            }
        }

        // ---- O += P @ V  (P built in registers from S fragments) ----
        #pragma unroll
        for (int jj = 0; jj < 4; jj++) {
            uint32_t pa0 = packh2(s[2 * jj][0],     s[2 * jj][1]);
            uint32_t pa1 = packh2(s[2 * jj][2],     s[2 * jj][3]);
            uint32_t pa2 = packh2(s[2 * jj + 1][0], s[2 * jj + 1][1]);
            uint32_t pa3 = packh2(s[2 * jj + 1][2], s[2 * jj + 1][3]);
            #pragma unroll
            for (int p = 0; p < 4; p++) {
                uint32_t b0, b1, b2, b3;
                ldsm_x4_t(b0, b1, b2, b3, uVb + jj * 16 * 144 + p * 32 + offA);
                mma_f16(o[2 * p],     pa0, pa1, pa2, pa3, b0, b1);
                mma_f16(o[2 * p + 1], pa0, pa1, pa2, pa3, b2, b3);
            }
        }
    }

    // ---- normalize + write O (fp16) in [B, L, INNER] layout ----
    #pragma unroll
    for (int hh = 0; hh < 2; hh++) {
        float inv = 1.f / l_i[hh];
        int r = q0 + warp * 16 + g + 8 * hh;
        __half* dstp = &g_oh[(size_t)(b * LTOT + r) * INNER + h * DHEAD];
        #pragma unroll
        for (int nt = 0; nt < 8; nt++) {
            *(__half2*)&dstp[nt * 8 + 2 * qd] =
                __floats2half2_rn(o[nt][hh * 2] * inv, o[nt][hh * 2 + 1] * inv);
        }
    }
}

// ---------------------------------------------------------------------------
// kernel_launch
// ---------------------------------------------------------------------------
extern "C" void kernel_launch(void* const* d_in, const int* in_sizes, int n_in,
                              void* d_out, int out_size) {
    const float* nodes = (const float*)d_in[0];
    const float* edges = (const float*)d_in[1];
    const unsigned char* mask_raw = (const unsigned char*)d_in[2];
    const float* Wq  = (const float*)d_in[3];
    const float* bq  = (const float*)d_in[4];
    const float* Wk  = (const float*)d_in[5];
    const float* bk  = (const float*)d_in[6];
    const float* Wv  = (const float*)d_in[7];
    const float* bv  = (const float*)d_in[8];
    const float* Weq = (const float*)d_in[9];
    const float* beq = (const float*)d_in[10];
    const float* Wek = (const float*)d_in[11];
    const float* bek = (const float*)d_in[12];
    const float* Wev = (const float*)d_in[13];
    const float* bev = (const float*)d_in[14];
    const float* Wo  = (const float*)d_in[15];
    const float* bo  = (const float*)d_in[16];
    const float* Weo = (const float*)d_in[17];
    const float* beo = (const float*)d_in[18];
    float* out = (float*)d_out;

    void *qp, *kp, *vp, *op;
    cudaGetSymbolAddress(&qp, g_qh);
    cudaGetSymbolAddress(&kp, g_kh);
    cudaGetSymbolAddress(&vp, g_vh);
    cudaGetSymbolAddress(&op, g_oh);

    decode_mask_kernel<<<1, 256>>>(mask_raw);

    // Node Q/K/V projections fused (z): M=2048, K=128, N=512. Q scaled.
    gemm_f16_kernel<false><<<dim3(8, 16, 3), 256>>>(
        nodes, Wq, Wk, Wv, bq, bk, bv, qp, kp, vp,
        SCALE, 1.f, 1.f, 2048, 128, 512, 1024, 1024, 0, 0, 0);

    // Edge Q/K/V projections fused: M=4096, K=256, N=512, seq offset 1024
    gemm_f16_kernel<false><<<dim3(8, 32, 3), 256>>>(
        edges, Weq, Wek, Wev, beq, bek, bev, qp, kp, vp,
        SCALE, 1.f, 1.f, 4096, 256, 512, 2048, 2048, 0, 0, 1024);

    // Flash attention
    cudaFuncSetAttribute(attn_f16_kernel,
                         cudaFuncAttributeMaxDynamicSharedMemorySize, ATTN_SMEM_BYTES);
    attn_f16_kernel<<<dim3(LTOT / 128, BSZ * HEADS), 256, ATTN_SMEM_BYTES>>>();

    // Output projections (A = fp16 attention output, dst = fp32 d_out)
    gemm_f16_kernel<true><<<dim3(2, 16, 1), 256>>>(
        op, Wo, Wo, Wo, bo, bo, bo, out, out, out,
        1.f, 1.f, 1.f, 2048, 512, 128, 1024, 3072, 0, 1, 0);
    gemm_f16_kernel<true><<<dim3(4, 32, 1), 256>>>(
        op, Weo, Weo, Weo, beo, beo, beo,
        out + 2 * 1024 * 128, out + 2 * 1024 * 128, out + 2 * 1024 * 128,
        1.f, 1.f, 1.f, 4096, 512, 256, 2048, 3072, 1024, 1, 0);
}

// round 5
// speedup vs baseline: 8.4100x; 1.2920x over previous
#include <cuda_runtime.h>
#include <cuda_fp16.h>
#include <float.h>
#include <math.h>
#include <stdint.h>

// Problem constants
#define BSZ   2
#define NN    1024
#define EE    2048
#define LTOT  3072
#define HEADS 8
#define DHEAD 64
#define INNER 512
#define SCALE 0.125f
#define LOG2E 1.4426950408889634f

// Scratch (fp16 intermediates)
__device__ __half g_qh[BSZ * HEADS * LTOT * DHEAD];   // pre-scaled by SCALE*LOG2E
__device__ __half g_kh[BSZ * HEADS * LTOT * DHEAD];
__device__ __half g_vh[BSZ * HEADS * LTOT * DHEAD];
__device__ __half g_oh[BSZ * LTOT * INNER];
__device__ int    g_mask[BSZ * LTOT];
__device__ int    g_kidx[BSZ * LTOT];                 // compacted unmasked key indices
__device__ int    g_nk[BSZ];
__device__ float  g_vmean[BSZ * HEADS * DHEAD];       // per-(b,h) mean of V over all keys

// ---------------------------------------------------------------------------
// PTX helpers
// ---------------------------------------------------------------------------
__device__ __forceinline__ uint32_t sptr(const void* p) {
    return (uint32_t)__cvta_generic_to_shared(p);
}
__device__ __forceinline__ void ldsm_x4(uint32_t& r0, uint32_t& r1,
                                        uint32_t& r2, uint32_t& r3, uint32_t addr) {
    asm volatile("ldmatrix.sync.aligned.m8n8.x4.shared.b16 {%0,%1,%2,%3}, [%4];"
                 : "=r"(r0), "=r"(r1), "=r"(r2), "=r"(r3) : "r"(addr));
}
__device__ __forceinline__ void ldsm_x4_t(uint32_t& r0, uint32_t& r1,
                                          uint32_t& r2, uint32_t& r3, uint32_t addr) {
    asm volatile("ldmatrix.sync.aligned.m8n8.x4.trans.shared.b16 {%0,%1,%2,%3}, [%4];"
                 : "=r"(r0), "=r"(r1), "=r"(r2), "=r"(r3) : "r"(addr));
}
__device__ __forceinline__ void mma_f16(float c[4],
                                        uint32_t a0, uint32_t a1, uint32_t a2, uint32_t a3,
                                        uint32_t b0, uint32_t b1) {
    asm volatile(
        "mma.sync.aligned.m16n8k16.row.col.f32.f16.f16.f32 "
        "{%0,%1,%2,%3}, {%4,%5,%6,%7}, {%8,%9}, {%0,%1,%2,%3};"
        : "+f"(c[0]), "+f"(c[1]), "+f"(c[2]), "+f"(c[3])
        : "r"(a0), "r"(a1), "r"(a2), "r"(a3), "r"(b0), "r"(b1));
}
__device__ __forceinline__ void cp16(uint32_t dst, const void* src) {
    asm volatile("cp.async.cg.shared.global [%0], [%1], 16;" :: "r"(dst), "l"(src));
}
__device__ __forceinline__ void cp_commit() {
    asm volatile("cp.async.commit_group;");
}
__device__ __forceinline__ void cp_wait0() {
    asm volatile("cp.async.wait_group 0;");
}
__device__ __forceinline__ uint32_t packh2(float x, float y) {
    __half2 h = __floats2half2_rn(x, y);
    return *reinterpret_cast<uint32_t*>(&h);
}
__device__ __forceinline__ float fexp2(float x) {
    float y;
    asm("ex2.approx.ftz.f32 %0, %1;" : "=f"(y) : "f"(x));
    return y;
}

// ---------------------------------------------------------------------------
// Mask decode + per-batch compaction of unmasked key indices.
// grid = BSZ (one block per batch), 256 threads, 12 elems/thread.
// Width heuristic as before (1-byte vs 4-byte bool serialization).
// ---------------------------------------------------------------------------
__global__ void mask_kernel(const unsigned char* __restrict__ raw) {
    __shared__ int partial[256];
    __shared__ int pfx[256];
    const int n = BSZ * LTOT;
    const int b = blockIdx.x;
    const int tid = threadIdx.x;

    int cnt = 0;
    for (int i = tid; i < n; i += 256) cnt += (raw[i] != 0);
    partial[tid] = cnt;
    __syncthreads();
    for (int s = 128; s > 0; s >>= 1) {
        if (tid < s) partial[tid] += partial[tid + s];
        __syncthreads();
    }
    const int width1 = partial[0] > (n * 3 / 8);
    const int* raw32 = (const int*)raw;

    int bits[12];
    int myc = 0;
    #pragma unroll
    for (int i = 0; i < 12; i++) {
        int li = tid * 12 + i;
        int gi = b * LTOT + li;
        int v = width1 ? (raw[gi] != 0) : (raw32[gi] != 0);
        g_mask[gi] = v;
        bits[i] = v;
        myc += v;
    }
    pfx[tid] = myc;
    __syncthreads();
    if (tid == 0) {
        int acc = 0;
        for (int t = 0; t < 256; t++) { int c = pfx[t]; pfx[t] = acc; acc += c; }
        g_nk[b] = acc;
    }
    __syncthreads();
    int off = b * LTOT + pfx[tid];
    #pragma unroll
    for (int i = 0; i < 12; i++)
        if (bits[i]) g_kidx[off++] = tid * 12 + i;
}

// ---------------------------------------------------------------------------
// Per-(b,h) mean of V over ALL keys (used for fully-masked query rows:
// reference gives uniform softmax over all 3072 keys).
// ---------------------------------------------------------------------------
__global__ void vmean_kernel() {
    const int bh = blockIdx.x;
    const __half* Vg = g_vh + (size_t)bh * LTOT * DHEAD;
    const int tid = threadIdx.x;
    const int d = tid & 63, c = tid >> 6;     // 4 row-chunks
    float s = 0.f;
    for (int r = c; r < LTOT; r += 4)
        s += __half2float(Vg[(size_t)r * DHEAD + d]);
    __shared__ float sm[256];
    sm[tid] = s;
    __syncthreads();
    if (c == 0)
        g_vmean[bh * DHEAD + d] =
            (sm[d] + sm[64 + d] + sm[128 + d] + sm[192 + d]) * (1.0f / LTOT);
}

// ---------------------------------------------------------------------------
// fp16 tensor-core GEMM (unchanged from round 4): C = (A' @ W + bias) * scale
// ---------------------------------------------------------------------------
template <bool AHALF>
__global__ __launch_bounds__(256) void gemm_f16_kernel(
        const void* __restrict__ Ap,
        const float* W0, const float* W1, const float* W2,
        const float* b0p, const float* b1p, const float* b2p,
        void* d0p, void* d1p, void* d2p,
        float s0, float s1, float s2,
        int M, int K, int Ncols,
        int rowsPerBatch, int aBatchStride, int aSeqOff,
        int dstMode, int dstSeqOff) {
    __shared__ __align__(16) __half sA[128 * 40];
    __shared__ __align__(16) __half sW[32 * 72];

    const int z = blockIdx.z;
    const float* W    = (z == 0) ? W0 : (z == 1) ? W1 : W2;
    const float* bias = (z == 0) ? b0p : (z == 1) ? b1p : b2p;
    void* dst         = (z == 0) ? d0p : (z == 1) ? d1p : d2p;
    const float scl   = (z == 0) ? s0 : (z == 1) ? s1 : s2;

    const int tid = threadIdx.x;
    const int warp = tid >> 5, lane = tid & 31;
    const int g = lane >> 2, qd = lane & 3;
    const int wy = warp >> 1, wx = warp & 1;
    const int row0 = blockIdx.y * 128;
    const int col0 = blockIdx.x * 64;

    const uint32_t uA = sptr(sA);
    const uint32_t uW = sptr(sW);
    const int offA = ((lane & 7) + ((lane >> 3) & 1) * 8) * 80 + (lane >> 4) * 16;
    const int offW = ((lane & 7) + ((lane >> 3) & 1) * 8) * 144 + (lane >> 4) * 16;

    float acc[2][4][4] = {};

    for (int kt = 0; kt < K; kt += 32) {
        #pragma unroll
        for (int t = 0; t < 8; t++) {
            int idx = tid + t * 256;
            int i = idx >> 4, k2 = idx & 15;
            int m = row0 + i;
            int bb = m / rowsPerBatch;
            int r = m - bb * rowsPerBatch;
            size_t arow = (size_t)(bb * aBatchStride + aSeqOff + r) * K + kt + 2 * k2;
            if (AHALF) {
                ((__half2*)sA)[i * 20 + k2] = *(const __half2*)((const __half*)Ap + arow);
            } else {
                float2 v = *(const float2*)((const float*)Ap + arow);
                ((__half2*)sA)[i * 20 + k2] = __floats2half2_rn(v.x, v.y);
            }
        }
        #pragma unroll
        for (int t = 0; t < 4; t++) {
            int idx = tid + t * 256;
            int kr = idx >> 5, n2 = idx & 31;
            float2 v = *(const float2*)&W[(size_t)(kt + kr) * Ncols + col0 + 2 * n2];
            ((__half2*)sW)[kr * 36 + n2] = __floats2half2_rn(v.x, v.y);
        }
        __syncthreads();

        #pragma unroll
        for (int kk = 0; kk < 2; kk++) {
            uint32_t a[2][4];
            #pragma unroll
            for (int mt = 0; mt < 2; mt++)
                ldsm_x4(a[mt][0], a[mt][1], a[mt][2], a[mt][3],
                        uA + (wy * 32 + mt * 16) * 80 + kk * 32 + offA);
            #pragma unroll
            for (int p = 0; p < 2; p++) {
                uint32_t b0, b1, b2, b3;
                ldsm_x4_t(b0, b1, b2, b3,
                          uW + kk * 16 * 144 + (wx * 32 + p * 16) * 2 + offW);
                mma_f16(acc[0][2 * p],     a[0][0], a[0][1], a[0][2], a[0][3], b0, b1);
                mma_f16(acc[0][2 * p + 1], a[0][0], a[0][1], a[0][2], a[0][3], b2, b3);
                mma_f16(acc[1][2 * p],     a[1][0], a[1][1], a[1][2], a[1][3], b0, b1);
                mma_f16(acc[1][2 * p + 1], a[1][0], a[1][1], a[1][2], a[1][3], b2, b3);
            }
        }
        __syncthreads();
    }

    #pragma unroll
    for (int mt = 0; mt < 2; mt++) {
        #pragma unroll
        for (int hh = 0; hh < 2; hh++) {
            int m = row0 + wy * 32 + mt * 16 + g + 8 * hh;
            int bb = m / rowsPerBatch;
            int r = m - bb * rowsPerBatch;
            #pragma unroll
            for (int n = 0; n < 4; n++) {
                int c = col0 + wx * 32 + n * 8 + 2 * qd;
                float v0 = (acc[mt][n][hh * 2 + 0] + bias[c]) * scl;
                float v1 = (acc[mt][n][hh * 2 + 1] + bias[c + 1]) * scl;
                if (dstMode == 0) {
                    int hidx = c >> 6, d = c & 63;
                    __half* dh = (__half*)dst;
                    *(__half2*)&dh[((size_t)(bb * HEADS + hidx) * LTOT +
                                    dstSeqOff + r) * DHEAD + d] = __floats2half2_rn(v0, v1);
                } else {
                    float* df = (float*)dst;
                    *(float2*)&df[(size_t)m * Ncols + c] = make_float2(v0, v1);
                }
            }
        }
    }
}

// ---------------------------------------------------------------------------
// Flash attention over COMPACTED (unmasked) keys only.
// Masked keys contribute exactly 0 in the reference (exp(-FLT_MAX - m) == 0),
// so dropping them is exact. Fully-masked query rows (qm=0) get the uniform
// result = mean of V over ALL keys, patched in at the epilogue via g_vmean.
// Softmax in base-2 domain (Q pre-scaled by SCALE*LOG2E), ex2.approx.
// Br=128, Bc=64, 256 threads = 8 warps; K/V gathered via cp.async, dbl-buffered.
// ---------------------------------------------------------------------------
#define KVSTR 72
#define KVBUF_H (64 * KVSTR)
#define KVBUF_B (KVBUF_H * 2)
#define ATTN_SMEM_BYTES (4 * KVBUF_B)

__global__ __launch_bounds__(256, 2) void attn_f16_kernel() {
    extern __shared__ __align__(16) char smraw[];
    __half* Kh = (__half*)smraw;                 // [2][64][72]
    __half* Vh = (__half*)(smraw + 2 * KVBUF_B); // [2][64][72]

    const int tid = threadIdx.x;
    const int warp = tid >> 5, lane = tid & 31;
    const int g = lane >> 2, qd = lane & 3;
    const int bh = blockIdx.y, b = bh >> 3, h = bh & 7;
    const int q0 = blockIdx.x * 128;

    const __half* Qg = g_qh + (size_t)bh * LTOT * DHEAD;
    const __half* Kg = g_kh + (size_t)bh * LTOT * DHEAD;
    const __half* Vg = g_vh + (size_t)bh * LTOT * DHEAD;
    const int* kidx = g_kidx + b * LTOT;
    const int nk = g_nk[b];
    const int NIT = (nk + 63) >> 6;

    const uint32_t uK = sptr(Kh), uV = sptr(Vh);
    const int offA = ((lane & 7) + ((lane >> 3) & 1) * 8) * 144 + (lane >> 4) * 16;
    const int offK = ((lane & 7) + ((lane >> 4) & 1) * 8) * 144 + ((lane >> 3) & 1) * 16;

    const int prow = tid >> 3;                   // 0..31
    const int pch = (tid & 7) * 16;              // byte offset 0..112

    // Prologue: gather-load tile 0
    if (NIT > 0) {
        #pragma unroll
        for (int rr = 0; rr < 2; rr++) {
            int r = prow + rr * 32;
            int idx = (r < nk) ? kidx[r] : 0;
            cp16(uK + r * 144 + pch, Kg + (size_t)idx * 64 + (pch >> 1));
            cp16(uV + r * 144 + pch, Vg + (size_t)idx * 64 + (pch >> 1));
        }
        cp_commit();
    }

    // Q fragments, register-resident (pre-scaled by SCALE*LOG2E in gmem)
    uint32_t qa[4][4];
    {
        const __half* qr0 = Qg + (size_t)(q0 + warp * 16 + g) * DHEAD;
        const __half* qr1 = qr0 + 8 * DHEAD;
        #pragma unroll
        for (int kk = 0; kk < 4; kk++) {
            int c = kk * 16 + 2 * qd;
            qa[kk][0] = *(const uint32_t*)(qr0 + c);
            qa[kk][1] = *(const uint32_t*)(qr1 + c);
            qa[kk][2] = *(const uint32_t*)(qr0 + c + 8);
            qa[kk][3] = *(const uint32_t*)(qr1 + c + 8);
        }
    }

    const int qm0 = g_mask[b * LTOT + q0 + warp * 16 + g];
    const int qm1 = g_mask[b * LTOT + q0 + warp * 16 + g + 8];

    float m_i[2] = {-FLT_MAX, -FLT_MAX};
    float l_i[2] = {0.f, 0.f};
    float o[8][4] = {};

    for (int it = 0; it < NIT; it++) {
        const int bf = it & 1;
        const int k0 = it * 64;
        cp_wait0();
        __syncthreads();

        if (it + 1 < NIT) {
            uint32_t uKn = uK + (bf ^ 1) * KVBUF_B;
            uint32_t uVn = uV + (bf ^ 1) * KVBUF_B;
            #pragma unroll
            for (int rr = 0; rr < 2; rr++) {
                int r = prow + rr * 32;
                int gi = k0 + 64 + r;
                int idx = (gi < nk) ? kidx[gi] : 0;
                cp16(uKn + r * 144 + pch, Kg + (size_t)idx * 64 + (pch >> 1));
                cp16(uVn + r * 144 + pch, Vg + (size_t)idx * 64 + (pch >> 1));
            }
            cp_commit();
        }

        const uint32_t uKb = uK + bf * KVBUF_B;
        const uint32_t uVb = uV + bf * KVBUF_B;

        // ---- S = Q @ K^T ----
        float s[8][4] = {};
        #pragma unroll
        for (int kk = 0; kk < 4; kk++) {
            #pragma unroll
            for (int p = 0; p < 4; p++) {
                uint32_t b0, b1, b2, b3;
                ldsm_x4(b0, b1, b2, b3, uKb + p * 16 * 144 + kk * 32 + offK);
                mma_f16(s[2 * p],     qa[kk][0], qa[kk][1], qa[kk][2], qa[kk][3], b0, b1);
                mma_f16(s[2 * p + 1], qa[kk][0], qa[kk][1], qa[kk][2], qa[kk][3], b2, b3);
            }
        }

        // ---- tail masking only (all compacted keys are valid) ----
        if (k0 + 64 > nk) {
            #pragma unroll
            for (int nt = 0; nt < 8; nt++) {
                int j0 = k0 + nt * 8 + 2 * qd;
                if (j0 >= nk)     { s[nt][0] = -FLT_MAX; s[nt][2] = -FLT_MAX; }
                if (j0 + 1 >= nk) { s[nt][1] = -FLT_MAX; s[nt][3] = -FLT_MAX; }
            }
        }

        // ---- online softmax (base-2) ----
        #pragma unroll
        for (int hh = 0; hh < 2; hh++) {
            float mx = -FLT_MAX;
            #pragma unroll
            for (int nt = 0; nt < 8; nt++)
                mx = fmaxf(mx, fmaxf(s[nt][hh * 2], s[nt][hh * 2 + 1]));
            mx = fmaxf(mx, __shfl_xor_sync(0xffffffffu, mx, 1));
            mx = fmaxf(mx, __shfl_xor_sync(0xffffffffu, mx, 2));
            float mnew = fmaxf(m_i[hh], mx);
            float corr = fexp2(m_i[hh] - mnew);
            m_i[hh] = mnew;
            float rs = 0.f;
            #pragma unroll
            for (int nt = 0; nt < 8; nt++) {
                float p0 = fexp2(s[nt][hh * 2]     - mnew);
                float p1 = fexp2(s[nt][hh * 2 + 1] - mnew);
                rs += p0 + p1;
                s[nt][hh * 2]     = p0;
                s[nt][hh * 2 + 1] = p1;
            }
            rs += __shfl_xor_sync(0xffffffffu, rs, 1);
            rs += __shfl_xor_sync(0xffffffffu, rs, 2);
            l_i[hh] = l_i[hh] * corr + rs;
            #pragma unroll
            for (int nt = 0; nt < 8; nt++) {
                o[nt][hh * 2]     *= corr;
                o[nt][hh * 2 + 1] *= corr;
            }
        }

        // ---- O += P @ V (P in registers; C-frag == A-frag layout) ----
        #pragma unroll
        for (int jj = 0; jj < 4; jj++) {
            uint32_t pa0 = packh2(s[2 * jj][0],     s[2 * jj][1]);
            uint32_t pa1 = packh2(s[2 * jj][2],     s[2 * jj][3]);
            uint32_t pa2 = packh2(s[2 * jj + 1][0], s[2 * jj + 1][1]);
            uint32_t pa3 = packh2(s[2 * jj + 1][2], s[2 * jj + 1][3]);
            #pragma unroll
            for (int p = 0; p < 4; p++) {
                uint32_t b0, b1, b2, b3;
                ldsm_x4_t(b0, b1, b2, b3, uVb + jj * 16 * 144 + p * 32 + offA);
                mma_f16(o[2 * p],     pa0, pa1, pa2, pa3, b0, b1);
                mma_f16(o[2 * p + 1], pa0, pa1, pa2, pa3, b2, b3);
            }
        }
    }

    // ---- epilogue: normalize; masked rows get vmean ----
    const float* vm = g_vmean + bh * DHEAD;
    #pragma unroll
    for (int hh = 0; hh < 2; hh++) {
        const int qm = hh ? qm1 : qm0;
        const bool masked = (qm == 0) || (nk == 0);
        float inv = masked ? 0.f : (1.f / l_i[hh]);
        int r = q0 + warp * 16 + g + 8 * hh;
        __half* dstp = &g_oh[(size_t)(b * LTOT + r) * INNER + h * DHEAD];
        #pragma unroll
        for (int nt = 0; nt < 8; nt++) {
            int d0 = nt * 8 + 2 * qd;
            float v0, v1;
            if (masked) { v0 = vm[d0]; v1 = vm[d0 + 1]; }
            else { v0 = o[nt][hh * 2] * inv; v1 = o[nt][hh * 2 + 1] * inv; }
            *(__half2*)&dstp[d0] = __floats2half2_rn(v0, v1);
        }
    }
}

// ---------------------------------------------------------------------------
// kernel_launch
// ---------------------------------------------------------------------------
extern "C" void kernel_launch(void* const* d_in, const int* in_sizes, int n_in,
                              void* d_out, int out_size) {
    const float* nodes = (const float*)d_in[0];
    const float* edges = (const float*)d_in[1];
    const unsigned char* mask_raw = (const unsigned char*)d_in[2];
    const float* Wq  = (const float*)d_in[3];
    const float* bq  = (const float*)d_in[4];
    const float* Wk  = (const float*)d_in[5];
    const float* bk  = (const float*)d_in[6];
    const float* Wv  = (const float*)d_in[7];
    const float* bv  = (const float*)d_in[8];
    const float* Weq = (const float*)d_in[9];
    const float* beq = (const float*)d_in[10];
    const float* Wek = (const float*)d_in[11];
    const float* bek = (const float*)d_in[12];
    const float* Wev = (const float*)d_in[13];
    const float* bev = (const float*)d_in[14];
    const float* Wo  = (const float*)d_in[15];
    const float* bo  = (const float*)d_in[16];
    const float* Weo = (const float*)d_in[17];
    const float* beo = (const float*)d_in[18];
    float* out = (float*)d_out;

    void *qp, *kp, *vp, *op;
    cudaGetSymbolAddress(&qp, g_qh);
    cudaGetSymbolAddress(&kp, g_kh);
    cudaGetSymbolAddress(&vp, g_vh);
    cudaGetSymbolAddress(&op, g_oh);

    mask_kernel<<<BSZ, 256>>>(mask_raw);

    const float qscale = SCALE * LOG2E;

    // Node Q/K/V projections fused (z): M=2048, K=128, N=512
    gemm_f16_kernel<false><<<dim3(8, 16, 3), 256>>>(
        nodes, Wq, Wk, Wv, bq, bk, bv, qp, kp, vp,
        qscale, 1.f, 1.f, 2048, 128, 512, 1024, 1024, 0, 0, 0);

    // Edge Q/K/V projections fused: M=4096, K=256, N=512, seq offset 1024
    gemm_f16_kernel<false><<<dim3(8, 32, 3), 256>>>(
        edges, Weq, Wek, Wev, beq, bek, bev, qp, kp, vp,
        qscale, 1.f, 1.f, 4096, 256, 512, 2048, 2048, 0, 0, 1024);

    // V mean per (b,h) for fully-masked query rows
    vmean_kernel<<<BSZ * HEADS, 256>>>();

    // Flash attention over compacted keys
    cudaFuncSetAttribute(attn_f16_kernel,
                         cudaFuncAttributeMaxDynamicSharedMemorySize, ATTN_SMEM_BYTES);
    attn_f16_kernel<<<dim3(LTOT / 128, BSZ * HEADS), 256, ATTN_SMEM_BYTES>>>();

    // Output projections
    gemm_f16_kernel<true><<<dim3(2, 16, 1), 256>>>(
        op, Wo, Wo, Wo, bo, bo, bo, out, out, out,
        1.f, 1.f, 1.f, 2048, 512, 128, 1024, 3072, 0, 1, 0);
    gemm_f16_kernel<true><<<dim3(4, 32, 1), 256>>>(
        op, Weo, Weo, Weo, beo, beo, beo,
        out + 2 * 1024 * 128, out + 2 * 1024 * 128, out + 2 * 1024 * 128,
        1.f, 1.f, 1.f, 4096, 512, 256, 2048, 3072, 1024, 1, 0);
}

// round 6
// speedup vs baseline: 9.7791x; 1.1628x over previous
#include <cuda_runtime.h>
#include <cuda_fp16.h>
#include <float.h>
#include <math.h>
#include <stdint.h>

// Problem constants
#define BSZ   2
#define NN    1024
#define EE    2048
#define LTOT  3072
#define HEADS 8
#define DHEAD 64
#define INNER 512
#define SCALE 0.125f
#define LOG2E 1.4426950408889634f

// Scratch (fp16 intermediates)
__device__ __half g_qh[BSZ * HEADS * LTOT * DHEAD];   // pre-scaled by SCALE*LOG2E
__device__ __half g_kh[BSZ * HEADS * LTOT * DHEAD];
__device__ __half g_vh[BSZ * HEADS * LTOT * DHEAD];
__device__ __half g_oh[BSZ * LTOT * INNER];
__device__ int    g_mask[BSZ * LTOT];
__device__ int    g_kidx[BSZ * LTOT];                 // compacted unmasked key indices
__device__ int    g_nk[BSZ];
__device__ float  g_vpart[BSZ * HEADS * 4 * DHEAD];   // partial V sums (4 chunks/bh)

// ---------------------------------------------------------------------------
// PTX helpers
// ---------------------------------------------------------------------------
__device__ __forceinline__ uint32_t sptr(const void* p) {
    return (uint32_t)__cvta_generic_to_shared(p);
}
__device__ __forceinline__ void ldsm_x4(uint32_t& r0, uint32_t& r1,
                                        uint32_t& r2, uint32_t& r3, uint32_t addr) {
    asm volatile("ldmatrix.sync.aligned.m8n8.x4.shared.b16 {%0,%1,%2,%3}, [%4];"
                 : "=r"(r0), "=r"(r1), "=r"(r2), "=r"(r3) : "r"(addr));
}
__device__ __forceinline__ void ldsm_x4_t(uint32_t& r0, uint32_t& r1,
                                          uint32_t& r2, uint32_t& r3, uint32_t addr) {
    asm volatile("ldmatrix.sync.aligned.m8n8.x4.trans.shared.b16 {%0,%1,%2,%3}, [%4];"
                 : "=r"(r0), "=r"(r1), "=r"(r2), "=r"(r3) : "r"(addr));
}
__device__ __forceinline__ void mma_f16(float c[4],
                                        uint32_t a0, uint32_t a1, uint32_t a2, uint32_t a3,
                                        uint32_t b0, uint32_t b1) {
    asm volatile(
        "mma.sync.aligned.m16n8k16.row.col.f32.f16.f16.f32 "
        "{%0,%1,%2,%3}, {%4,%5,%6,%7}, {%8,%9}, {%0,%1,%2,%3};"
        : "+f"(c[0]), "+f"(c[1]), "+f"(c[2]), "+f"(c[3])
        : "r"(a0), "r"(a1), "r"(a2), "r"(a3), "r"(b0), "r"(b1));
}
__device__ __forceinline__ void cp16(uint32_t dst, const void* src) {
    asm volatile("cp.async.cg.shared.global [%0], [%1], 16;" :: "r"(dst), "l"(src));
}
__device__ __forceinline__ void cp_commit() {
    asm volatile("cp.async.commit_group;");
}
__device__ __forceinline__ void cp_wait0() {
    asm volatile("cp.async.wait_group 0;");
}
__device__ __forceinline__ uint32_t packh2(float x, float y) {
    __half2 h = __floats2half2_rn(x, y);
    return *reinterpret_cast<uint32_t*>(&h);
}
__device__ __forceinline__ float fexp2(float x) {
    float y;
    asm("ex2.approx.ftz.f32 %0, %1;" : "=f"(y) : "f"(x));
    return y;
}

// ---------------------------------------------------------------------------
// Mask decode + per-batch compaction of unmasked key indices.
// ---------------------------------------------------------------------------
__global__ void mask_kernel(const unsigned char* __restrict__ raw) {
    __shared__ int partial[256];
    __shared__ int pfx[256];
    const int n = BSZ * LTOT;
    const int b = blockIdx.x;
    const int tid = threadIdx.x;

    int cnt = 0;
    for (int i = tid; i < n; i += 256) cnt += (raw[i] != 0);
    partial[tid] = cnt;
    __syncthreads();
    for (int s = 128; s > 0; s >>= 1) {
        if (tid < s) partial[tid] += partial[tid + s];
        __syncthreads();
    }
    const int width1 = partial[0] > (n * 3 / 8);
    const int* raw32 = (const int*)raw;

    int bits[12];
    int myc = 0;
    #pragma unroll
    for (int i = 0; i < 12; i++) {
        int li = tid * 12 + i;
        int gi = b * LTOT + li;
        int v = width1 ? (raw[gi] != 0) : (raw32[gi] != 0);
        g_mask[gi] = v;
        bits[i] = v;
        myc += v;
    }
    pfx[tid] = myc;
    __syncthreads();
    if (tid == 0) {
        int acc = 0;
        for (int t = 0; t < 256; t++) { int c = pfx[t]; pfx[t] = acc; acc += c; }
        g_nk[b] = acc;
    }
    __syncthreads();
    int off = b * LTOT + pfx[tid];
    #pragma unroll
    for (int i = 0; i < 12; i++)
        if (bits[i]) g_kidx[off++] = tid * 12 + i;
}

// ---------------------------------------------------------------------------
// Partial V sums: grid = BSZ*HEADS*4 (4 row-chunks of 768 per (b,h)).
// 256 threads; 32 rows in flight, 8 threads/row, uint4 loads (8 halfs = 16B).
// Fully coalesced (128B rows). Partials combined in the attention epilogue.
// ---------------------------------------------------------------------------
__global__ void vmean_kernel() {
    const int bh = blockIdx.x >> 2;
    const int chunk = blockIdx.x & 3;
    const __half* Vg = g_vh + (size_t)bh * LTOT * DHEAD + (size_t)chunk * 768 * DHEAD;
    const int tid = threadIdx.x;
    const int rg = tid >> 3;           // 0..31 row group
    const int dg = tid & 7;            // 0..7, covers d = dg*8 .. dg*8+7

    float acc[8] = {};
    for (int r = rg; r < 768; r += 32) {
        uint4 u = *(const uint4*)(Vg + (size_t)r * DHEAD + dg * 8);
        const __half2* h2 = (const __half2*)&u;
        #pragma unroll
        for (int j = 0; j < 4; j++) {
            float2 f = __half22float2(h2[j]);
            acc[2 * j]     += f.x;
            acc[2 * j + 1] += f.y;
        }
    }

    __shared__ float sm[256][8];
    #pragma unroll
    for (int j = 0; j < 8; j++) sm[tid][j] = acc[j];
    __syncthreads();

    if (tid < DHEAD) {
        int d = tid;
        int srcdg = d >> 3, j = d & 7;
        float s = 0.f;
        #pragma unroll
        for (int r = 0; r < 32; r++) s += sm[srcdg + 8 * r][j];
        g_vpart[(bh * 4 + chunk) * DHEAD + d] = s;
    }
}

// ---------------------------------------------------------------------------
// fp16 tensor-core GEMM: C = (A' @ W + bias) * scale
// ---------------------------------------------------------------------------
template <bool AHALF>
__global__ __launch_bounds__(256) void gemm_f16_kernel(
        const void* __restrict__ Ap,
        const float* W0, const float* W1, const float* W2,
        const float* b0p, const float* b1p, const float* b2p,
        void* d0p, void* d1p, void* d2p,
        float s0, float s1, float s2,
        int M, int K, int Ncols,
        int rowsPerBatch, int aBatchStride, int aSeqOff,
        int dstMode, int dstSeqOff) {
    __shared__ __align__(16) __half sA[128 * 40];
    __shared__ __align__(16) __half sW[32 * 72];

    const int z = blockIdx.z;
    const float* W    = (z == 0) ? W0 : (z == 1) ? W1 : W2;
    const float* bias = (z == 0) ? b0p : (z == 1) ? b1p : b2p;
    void* dst         = (z == 0) ? d0p : (z == 1) ? d1p : d2p;
    const float scl   = (z == 0) ? s0 : (z == 1) ? s1 : s2;

    const int tid = threadIdx.x;
    const int warp = tid >> 5, lane = tid & 31;
    const int g = lane >> 2, qd = lane & 3;
    const int wy = warp >> 1, wx = warp & 1;
    const int row0 = blockIdx.y * 128;
    const int col0 = blockIdx.x * 64;

    const uint32_t uA = sptr(sA);
    const uint32_t uW = sptr(sW);
    const int offA = ((lane & 7) + ((lane >> 3) & 1) * 8) * 80 + (lane >> 4) * 16;
    const int offW = ((lane & 7) + ((lane >> 3) & 1) * 8) * 144 + (lane >> 4) * 16;

    float acc[2][4][4] = {};

    for (int kt = 0; kt < K; kt += 32) {
        #pragma unroll
        for (int t = 0; t < 8; t++) {
            int idx = tid + t * 256;
            int i = idx >> 4, k2 = idx & 15;
            int m = row0 + i;
            int bb = m / rowsPerBatch;
            int r = m - bb * rowsPerBatch;
            size_t arow = (size_t)(bb * aBatchStride + aSeqOff + r) * K + kt + 2 * k2;
            if (AHALF) {
                ((__half2*)sA)[i * 20 + k2] = *(const __half2*)((const __half*)Ap + arow);
            } else {
                float2 v = *(const float2*)((const float*)Ap + arow);
                ((__half2*)sA)[i * 20 + k2] = __floats2half2_rn(v.x, v.y);
            }
        }
        #pragma unroll
        for (int t = 0; t < 4; t++) {
            int idx = tid + t * 256;
            int kr = idx >> 5, n2 = idx & 31;
            float2 v = *(const float2*)&W[(size_t)(kt + kr) * Ncols + col0 + 2 * n2];
            ((__half2*)sW)[kr * 36 + n2] = __floats2half2_rn(v.x, v.y);
        }
        __syncthreads();

        #pragma unroll
        for (int kk = 0; kk < 2; kk++) {
            uint32_t a[2][4];
            #pragma unroll
            for (int mt = 0; mt < 2; mt++)
                ldsm_x4(a[mt][0], a[mt][1], a[mt][2], a[mt][3],
                        uA + (wy * 32 + mt * 16) * 80 + kk * 32 + offA);
            #pragma unroll
            for (int p = 0; p < 2; p++) {
                uint32_t b0, b1, b2, b3;
                ldsm_x4_t(b0, b1, b2, b3,
                          uW + kk * 16 * 144 + (wx * 32 + p * 16) * 2 + offW);
                mma_f16(acc[0][2 * p],     a[0][0], a[0][1], a[0][2], a[0][3], b0, b1);
                mma_f16(acc[0][2 * p + 1], a[0][0], a[0][1], a[0][2], a[0][3], b2, b3);
                mma_f16(acc[1][2 * p],     a[1][0], a[1][1], a[1][2], a[1][3], b0, b1);
                mma_f16(acc[1][2 * p + 1], a[1][0], a[1][1], a[1][2], a[1][3], b2, b3);
            }
        }
        __syncthreads();
    }

    #pragma unroll
    for (int mt = 0; mt < 2; mt++) {
        #pragma unroll
        for (int hh = 0; hh < 2; hh++) {
            int m = row0 + wy * 32 + mt * 16 + g + 8 * hh;
            int bb = m / rowsPerBatch;
            int r = m - bb * rowsPerBatch;
            #pragma unroll
            for (int n = 0; n < 4; n++) {
                int c = col0 + wx * 32 + n * 8 + 2 * qd;
                float v0 = (acc[mt][n][hh * 2 + 0] + bias[c]) * scl;
                float v1 = (acc[mt][n][hh * 2 + 1] + bias[c + 1]) * scl;
                if (dstMode == 0) {
                    int hidx = c >> 6, d = c & 63;
                    __half* dh = (__half*)dst;
                    *(__half2*)&dh[((size_t)(bb * HEADS + hidx) * LTOT +
                                    dstSeqOff + r) * DHEAD + d] = __floats2half2_rn(v0, v1);
                } else {
                    float* df = (float*)dst;
                    *(float2*)&df[(size_t)m * Ncols + c] = make_float2(v0, v1);
                }
            }
        }
    }
}

// ---------------------------------------------------------------------------
// Flash attention over COMPACTED (unmasked) keys. Masked keys contribute
// exactly 0 in the reference. Fully-masked query rows get the uniform result
// = mean of V over ALL keys (combined from g_vpart in the epilogue).
// Softmax base-2 (Q pre-scaled by SCALE*LOG2E), ex2.approx.
// ---------------------------------------------------------------------------
#define KVSTR 72
#define KVBUF_H (64 * KVSTR)
#define KVBUF_B (KVBUF_H * 2)
#define ATTN_SMEM_BYTES (4 * KVBUF_B)

__global__ __launch_bounds__(256, 2) void attn_f16_kernel() {
    extern __shared__ __align__(16) char smraw[];
    __half* Kh = (__half*)smraw;                 // [2][64][72]
    __half* Vh = (__half*)(smraw + 2 * KVBUF_B); // [2][64][72]

    const int tid = threadIdx.x;
    const int warp = tid >> 5, lane = tid & 31;
    const int g = lane >> 2, qd = lane & 3;
    const int bh = blockIdx.y, b = bh >> 3, h = bh & 7;
    const int q0 = blockIdx.x * 128;

    const __half* Qg = g_qh + (size_t)bh * LTOT * DHEAD;
    const __half* Kg = g_kh + (size_t)bh * LTOT * DHEAD;
    const __half* Vg = g_vh + (size_t)bh * LTOT * DHEAD;
    const int* kidx = g_kidx + b * LTOT;
    const int nk = g_nk[b];
    const int NIT = (nk + 63) >> 6;

    const uint32_t uK = sptr(Kh), uV = sptr(Vh);
    const int offA = ((lane & 7) + ((lane >> 3) & 1) * 8) * 144 + (lane >> 4) * 16;
    const int offK = ((lane & 7) + ((lane >> 4) & 1) * 8) * 144 + ((lane >> 3) & 1) * 16;

    const int prow = tid >> 3;                   // 0..31
    const int pch = (tid & 7) * 16;              // byte offset 0..112

    // Prologue: gather-load tile 0
    if (NIT > 0) {
        #pragma unroll
        for (int rr = 0; rr < 2; rr++) {
            int r = prow + rr * 32;
            int idx = (r < nk) ? kidx[r] : 0;
            cp16(uK + r * 144 + pch, Kg + (size_t)idx * 64 + (pch >> 1));
            cp16(uV + r * 144 + pch, Vg + (size_t)idx * 64 + (pch >> 1));
        }
        cp_commit();
    }

    // Q fragments, register-resident (pre-scaled by SCALE*LOG2E in gmem)
    uint32_t qa[4][4];
    {
        const __half* qr0 = Qg + (size_t)(q0 + warp * 16 + g) * DHEAD;
        const __half* qr1 = qr0 + 8 * DHEAD;
        #pragma unroll
        for (int kk = 0; kk < 4; kk++) {
            int c = kk * 16 + 2 * qd;
            qa[kk][0] = *(const uint32_t*)(qr0 + c);
            qa[kk][1] = *(const uint32_t*)(qr1 + c);
            qa[kk][2] = *(const uint32_t*)(qr0 + c + 8);
            qa[kk][3] = *(const uint32_t*)(qr1 + c + 8);
        }
    }

    const int qm0 = g_mask[b * LTOT + q0 + warp * 16 + g];
    const int qm1 = g_mask[b * LTOT + q0 + warp * 16 + g + 8];

    float m_i[2] = {-FLT_MAX, -FLT_MAX};
    float l_i[2] = {0.f, 0.f};
    float o[8][4] = {};

    for (int it = 0; it < NIT; it++) {
        const int bf = it & 1;
        const int k0 = it * 64;
        cp_wait0();
        __syncthreads();

        if (it + 1 < NIT) {
            uint32_t uKn = uK + (bf ^ 1) * KVBUF_B;
            uint32_t uVn = uV + (bf ^ 1) * KVBUF_B;
            #pragma unroll
            for (int rr = 0; rr < 2; rr++) {
                int r = prow + rr * 32;
                int gi = k0 + 64 + r;
                int idx = (gi < nk) ? kidx[gi] : 0;
                cp16(uKn + r * 144 + pch, Kg + (size_t)idx * 64 + (pch >> 1));
                cp16(uVn + r * 144 + pch, Vg + (size_t)idx * 64 + (pch >> 1));
            }
            cp_commit();
        }

        const uint32_t uKb = uK + bf * KVBUF_B;
        const uint32_t uVb = uV + bf * KVBUF_B;

        // ---- S = Q @ K^T ----
        float s[8][4] = {};
        #pragma unroll
        for (int kk = 0; kk < 4; kk++) {
            #pragma unroll
            for (int p = 0; p < 4; p++) {
                uint32_t b0, b1, b2, b3;
                ldsm_x4(b0, b1, b2, b3, uKb + p * 16 * 144 + kk * 32 + offK);
                mma_f16(s[2 * p],     qa[kk][0], qa[kk][1], qa[kk][2], qa[kk][3], b0, b1);
                mma_f16(s[2 * p + 1], qa[kk][0], qa[kk][1], qa[kk][2], qa[kk][3], b2, b3);
            }
        }

        // ---- tail masking only (all compacted keys are valid) ----
        if (k0 + 64 > nk) {
            #pragma unroll
            for (int nt = 0; nt < 8; nt++) {
                int j0 = k0 + nt * 8 + 2 * qd;
                if (j0 >= nk)     { s[nt][0] = -FLT_MAX; s[nt][2] = -FLT_MAX; }
                if (j0 + 1 >= nk) { s[nt][1] = -FLT_MAX; s[nt][3] = -FLT_MAX; }
            }
        }

        // ---- online softmax (base-2) ----
        #pragma unroll
        for (int hh = 0; hh < 2; hh++) {
            float mx = -FLT_MAX;
            #pragma unroll
            for (int nt = 0; nt < 8; nt++)
                mx = fmaxf(mx, fmaxf(s[nt][hh * 2], s[nt][hh * 2 + 1]));
            mx = fmaxf(mx, __shfl_xor_sync(0xffffffffu, mx, 1));
            mx = fmaxf(mx, __shfl_xor_sync(0xffffffffu, mx, 2));
            float mnew = fmaxf(m_i[hh], mx);
            float corr = fexp2(m_i[hh] - mnew);
            m_i[hh] = mnew;
            float rs = 0.f;
            #pragma unroll
            for (int nt = 0; nt < 8; nt++) {
                float p0 = fexp2(s[nt][hh * 2]     - mnew);
                float p1 = fexp2(s[nt][hh * 2 + 1] - mnew);
                rs += p0 + p1;
                s[nt][hh * 2]     = p0;
                s[nt][hh * 2 + 1] = p1;
            }
            rs += __shfl_xor_sync(0xffffffffu, rs, 1);
            rs += __shfl_xor_sync(0xffffffffu, rs, 2);
            l_i[hh] = l_i[hh] * corr + rs;
            #pragma unroll
            for (int nt = 0; nt < 8; nt++) {
                o[nt][hh * 2]     *= corr;
                o[nt][hh * 2 + 1] *= corr;
            }
        }

        // ---- O += P @ V (P in registers; C-frag == A-frag layout) ----
        #pragma unroll
        for (int jj = 0; jj < 4; jj++) {
            uint32_t pa0 = packh2(s[2 * jj][0],     s[2 * jj][1]);
            uint32_t pa1 = packh2(s[2 * jj][2],     s[2 * jj][3]);
            uint32_t pa2 = packh2(s[2 * jj + 1][0], s[2 * jj + 1][1]);
            uint32_t pa3 = packh2(s[2 * jj + 1][2], s[2 * jj + 1][3]);
            #pragma unroll
            for (int p = 0; p < 4; p++) {
                uint32_t b0, b1, b2, b3;
                ldsm_x4_t(b0, b1, b2, b3, uVb + jj * 16 * 144 + p * 32 + offA);
                mma_f16(o[2 * p],     pa0, pa1, pa2, pa3, b0, b1);
                mma_f16(o[2 * p + 1], pa0, pa1, pa2, pa3, b2, b3);
            }
        }
    }

    // ---- epilogue: normalize; masked rows get mean of V over ALL keys ----
    const float* vp = g_vpart + bh * 4 * DHEAD;
    #pragma unroll
    for (int hh = 0; hh < 2; hh++) {
        const int qm = hh ? qm1 : qm0;
        const bool masked = (qm == 0) || (nk == 0);
        float inv = masked ? 0.f : (1.f / l_i[hh]);
        int r = q0 + warp * 16 + g + 8 * hh;
        __half* dstp = &g_oh[(size_t)(b * LTOT + r) * INNER + h * DHEAD];
        #pragma unroll
        for (int nt = 0; nt < 8; nt++) {
            int d0 = nt * 8 + 2 * qd;
            float v0, v1;
            if (masked) {
                v0 = (vp[d0] + vp[DHEAD + d0] + vp[2 * DHEAD + d0] + vp[3 * DHEAD + d0])
                     * (1.0f / LTOT);
                v1 = (vp[d0 + 1] + vp[DHEAD + d0 + 1] + vp[2 * DHEAD + d0 + 1] + vp[3 * DHEAD + d0 + 1])
                     * (1.0f / LTOT);
            } else {
                v0 = o[nt][hh * 2] * inv;
                v1 = o[nt][hh * 2 + 1] * inv;
            }
            *(__half2*)&dstp[d0] = __floats2half2_rn(v0, v1);
        }
    }
}

// ---------------------------------------------------------------------------
// kernel_launch
// ---------------------------------------------------------------------------
extern "C" void kernel_launch(void* const* d_in, const int* in_sizes, int n_in,
                              void* d_out, int out_size) {
    const float* nodes = (const float*)d_in[0];
    const float* edges = (const float*)d_in[1];
    const unsigned char* mask_raw = (const unsigned char*)d_in[2];
    const float* Wq  = (const float*)d_in[3];
    const float* bq  = (const float*)d_in[4];
    const float* Wk  = (const float*)d_in[5];
    const float* bk  = (const float*)d_in[6];
    const float* Wv  = (const float*)d_in[7];
    const float* bv  = (const float*)d_in[8];
    const float* Weq = (const float*)d_in[9];
    const float* beq = (const float*)d_in[10];
    const float* Wek = (const float*)d_in[11];
    const float* bek = (const float*)d_in[12];
    const float* Wev = (const float*)d_in[13];
    const float* bev = (const float*)d_in[14];
    const float* Wo  = (const float*)d_in[15];
    const float* bo  = (const float*)d_in[16];
    const float* Weo = (const float*)d_in[17];
    const float* beo = (const float*)d_in[18];
    float* out = (float*)d_out;

    void *qp, *kp, *vp, *op;
    cudaGetSymbolAddress(&qp, g_qh);
    cudaGetSymbolAddress(&kp, g_kh);
    cudaGetSymbolAddress(&vp, g_vh);
    cudaGetSymbolAddress(&op, g_oh);

    mask_kernel<<<BSZ, 256>>>(mask_raw);

    const float qscale = SCALE * LOG2E;

    // Node Q/K/V projections fused (z): M=2048, K=128, N=512
    gemm_f16_kernel<false><<<dim3(8, 16, 3), 256>>>(
        nodes, Wq, Wk, Wv, bq, bk, bv, qp, kp, vp,
        qscale, 1.f, 1.f, 2048, 128, 512, 1024, 1024, 0, 0, 0);

    // Edge Q/K/V projections fused: M=4096, K=256, N=512, seq offset 1024
    gemm_f16_kernel<false><<<dim3(8, 32, 3), 256>>>(
        edges, Weq, Wek, Wev, beq, bek, bev, qp, kp, vp,
        qscale, 1.f, 1.f, 4096, 256, 512, 2048, 2048, 0, 0, 1024);

    // Partial V sums per (b,h) for fully-masked query rows
    vmean_kernel<<<BSZ * HEADS * 4, 256>>>();

    // Flash attention over compacted keys
    cudaFuncSetAttribute(attn_f16_kernel,
                         cudaFuncAttributeMaxDynamicSharedMemorySize, ATTN_SMEM_BYTES);
    attn_f16_kernel<<<dim3(LTOT / 128, BSZ * HEADS), 256, ATTN_SMEM_BYTES>>>();

    // Output projections
    gemm_f16_kernel<true><<<dim3(2, 16, 1), 256>>>(
        op, Wo, Wo, Wo, bo, bo, bo, out, out, out,
        1.f, 1.f, 1.f, 2048, 512, 128, 1024, 3072, 0, 1, 0);
    gemm_f16_kernel<true><<<dim3(4, 32, 1), 256>>>(
        op, Weo, Weo, Weo, beo, beo, beo,
        out + 2 * 1024 * 128, out + 2 * 1024 * 128, out + 2 * 1024 * 128,
        1.f, 1.f, 1.f, 4096, 512, 256, 2048, 3072, 1024, 1, 0);
}

// round 7
// speedup vs baseline: 11.6806x; 1.1944x over previous
#include <cuda_runtime.h>
#include <cuda_fp16.h>
#include <float.h>
#include <math.h>
#include <stdint.h>

// Problem constants
#define BSZ   2
#define NN    1024
#define EE    2048
#define LTOT  3072
#define HEADS 8
#define DHEAD 64
#define INNER 512
#define SCALE 0.125f
#define LOG2E 1.4426950408889634f
#define NCH   8                                 // vmean chunks per (b,h)

// Scratch (fp16 intermediates)
__device__ __half g_qh[BSZ * HEADS * LTOT * DHEAD];   // pre-scaled by SCALE*LOG2E
__device__ __half g_kh[BSZ * HEADS * LTOT * DHEAD];
__device__ __half g_vh[BSZ * HEADS * LTOT * DHEAD];
__device__ __half g_oh[BSZ * LTOT * INNER];
__device__ int    g_mask[BSZ * LTOT];
__device__ int    g_kidx[BSZ * LTOT];                 // compacted unmasked indices
__device__ int    g_nk[BSZ];
__device__ float  g_vpart[BSZ * HEADS * NCH * DHEAD]; // partial V sums

// ---------------------------------------------------------------------------
// PTX helpers
// ---------------------------------------------------------------------------
__device__ __forceinline__ uint32_t sptr(const void* p) {
    return (uint32_t)__cvta_generic_to_shared(p);
}
__device__ __forceinline__ void ldsm_x4(uint32_t& r0, uint32_t& r1,
                                        uint32_t& r2, uint32_t& r3, uint32_t addr) {
    asm volatile("ldmatrix.sync.aligned.m8n8.x4.shared.b16 {%0,%1,%2,%3}, [%4];"
                 : "=r"(r0), "=r"(r1), "=r"(r2), "=r"(r3) : "r"(addr));
}
__device__ __forceinline__ void ldsm_x4_t(uint32_t& r0, uint32_t& r1,
                                          uint32_t& r2, uint32_t& r3, uint32_t addr) {
    asm volatile("ldmatrix.sync.aligned.m8n8.x4.trans.shared.b16 {%0,%1,%2,%3}, [%4];"
                 : "=r"(r0), "=r"(r1), "=r"(r2), "=r"(r3) : "r"(addr));
}
__device__ __forceinline__ void mma_f16(float c[4],
                                        uint32_t a0, uint32_t a1, uint32_t a2, uint32_t a3,
                                        uint32_t b0, uint32_t b1) {
    asm volatile(
        "mma.sync.aligned.m16n8k16.row.col.f32.f16.f16.f32 "
        "{%0,%1,%2,%3}, {%4,%5,%6,%7}, {%8,%9}, {%0,%1,%2,%3};"
        : "+f"(c[0]), "+f"(c[1]), "+f"(c[2]), "+f"(c[3])
        : "r"(a0), "r"(a1), "r"(a2), "r"(a3), "r"(b0), "r"(b1));
}
__device__ __forceinline__ void cp16(uint32_t dst, const void* src) {
    asm volatile("cp.async.cg.shared.global [%0], [%1], 16;" :: "r"(dst), "l"(src));
}
__device__ __forceinline__ void cp_commit() {
    asm volatile("cp.async.commit_group;");
}
__device__ __forceinline__ void cp_wait0() {
    asm volatile("cp.async.wait_group 0;");
}
__device__ __forceinline__ uint32_t packh2(float x, float y) {
    __half2 h = __floats2half2_rn(x, y);
    return *reinterpret_cast<uint32_t*>(&h);
}
__device__ __forceinline__ float fexp2(float x) {
    float y;
    asm("ex2.approx.ftz.f32 %0, %1;" : "=f"(y) : "f"(x));
    return y;
}

// ---------------------------------------------------------------------------
// Mask decode + per-batch compaction of unmasked indices.
// ---------------------------------------------------------------------------
__global__ void mask_kernel(const unsigned char* __restrict__ raw) {
    __shared__ int partial[256];
    __shared__ int pfx[256];
    const int n = BSZ * LTOT;
    const int b = blockIdx.x;
    const int tid = threadIdx.x;

    int cnt = 0;
    for (int i = tid; i < n; i += 256) cnt += (raw[i] != 0);
    partial[tid] = cnt;
    __syncthreads();
    for (int s = 128; s > 0; s >>= 1) {
        if (tid < s) partial[tid] += partial[tid + s];
        __syncthreads();
    }
    const int width1 = partial[0] > (n * 3 / 8);
    const int* raw32 = (const int*)raw;

    int bits[12];
    int myc = 0;
    #pragma unroll
    for (int i = 0; i < 12; i++) {
        int li = tid * 12 + i;
        int gi = b * LTOT + li;
        int v = width1 ? (raw[gi] != 0) : (raw32[gi] != 0);
        g_mask[gi] = v;
        bits[i] = v;
        myc += v;
    }
    pfx[tid] = myc;
    __syncthreads();
    if (tid == 0) {
        int acc = 0;
        for (int t = 0; t < 256; t++) { int c = pfx[t]; pfx[t] = acc; acc += c; }
        g_nk[b] = acc;
    }
    __syncthreads();
    int off = b * LTOT + pfx[tid];
    #pragma unroll
    for (int i = 0; i < 12; i++)
        if (bits[i]) g_kidx[off++] = tid * 12 + i;
}

// ---------------------------------------------------------------------------
// Partial V sums: grid = BSZ*HEADS*NCH (chunks of LTOT/NCH rows).
// ---------------------------------------------------------------------------
__global__ void vmean_kernel() {
    const int bh = blockIdx.x / NCH;
    const int chunk = blockIdx.x % NCH;
    const int CROWS = LTOT / NCH;                // 384
    const __half* Vg = g_vh + (size_t)bh * LTOT * DHEAD + (size_t)chunk * CROWS * DHEAD;
    const int tid = threadIdx.x;
    const int rg = tid >> 3;           // 0..31 row group
    const int dg = tid & 7;            // covers d = dg*8 .. dg*8+7

    float acc[8] = {};
    for (int r = rg; r < CROWS; r += 32) {
        uint4 u = *(const uint4*)(Vg + (size_t)r * DHEAD + dg * 8);
        const __half2* h2 = (const __half2*)&u;
        #pragma unroll
        for (int j = 0; j < 4; j++) {
            float2 f = __half22float2(h2[j]);
            acc[2 * j]     += f.x;
            acc[2 * j + 1] += f.y;
        }
    }

    __shared__ float sm[256][8];
    #pragma unroll
    for (int j = 0; j < 8; j++) sm[tid][j] = acc[j];
    __syncthreads();

    if (tid < DHEAD) {
        int d = tid;
        int srcdg = d >> 3, j = d & 7;
        float s = 0.f;
        #pragma unroll
        for (int r = 0; r < 32; r++) s += sm[srcdg + 8 * r][j];
        g_vpart[(bh * NCH + chunk) * DHEAD + d] = s;
    }
}

// ---------------------------------------------------------------------------
// Patch kernel: masked rows of g_oh get the uniform-softmax result
// (mean of V over ALL keys) for every head. grid = 96 (64 rows per block).
// ---------------------------------------------------------------------------
__global__ void patch_kernel() {
    const int blk = blockIdx.x;
    const int b = blk / 48;
    const int r0 = (blk % 48) * 64;
    const int tid = threadIdx.x;
    const int h = tid >> 5;                      // 0..7
    const int d = (tid & 31) * 2;                // 0..62
    const float* vp = g_vpart + (size_t)(b * HEADS + h) * NCH * DHEAD;
    float v0 = 0.f, v1 = 0.f;
    #pragma unroll
    for (int c = 0; c < NCH; c++) { v0 += vp[c * DHEAD + d]; v1 += vp[c * DHEAD + d + 1]; }
    const __half2 hv = __floats2half2_rn(v0 * (1.0f / LTOT), v1 * (1.0f / LTOT));

    __shared__ int msk[64];
    if (tid < 64) msk[tid] = g_mask[b * LTOT + r0 + tid];
    __syncthreads();

    for (int r = 0; r < 64; r++) {
        if (!msk[r])
            *(__half2*)&g_oh[(size_t)(b * LTOT + r0 + r) * INNER + h * DHEAD + d] = hv;
    }
}

// ---------------------------------------------------------------------------
// fp16 tensor-core GEMM: C = (A' @ W + bias) * scale  (unchanged)
// ---------------------------------------------------------------------------
template <bool AHALF>
__global__ __launch_bounds__(256) void gemm_f16_kernel(
        const void* __restrict__ Ap,
        const float* W0, const float* W1, const float* W2,
        const float* b0p, const float* b1p, const float* b2p,
        void* d0p, void* d1p, void* d2p,
        float s0, float s1, float s2,
        int M, int K, int Ncols,
        int rowsPerBatch, int aBatchStride, int aSeqOff,
        int dstMode, int dstSeqOff) {
    __shared__ __align__(16) __half sA[128 * 40];
    __shared__ __align__(16) __half sW[32 * 72];

    const int z = blockIdx.z;
    const float* W    = (z == 0) ? W0 : (z == 1) ? W1 : W2;
    const float* bias = (z == 0) ? b0p : (z == 1) ? b1p : b2p;
    void* dst         = (z == 0) ? d0p : (z == 1) ? d1p : d2p;
    const float scl   = (z == 0) ? s0 : (z == 1) ? s1 : s2;

    const int tid = threadIdx.x;
    const int warp = tid >> 5, lane = tid & 31;
    const int g = lane >> 2, qd = lane & 3;
    const int wy = warp >> 1, wx = warp & 1;
    const int row0 = blockIdx.y * 128;
    const int col0 = blockIdx.x * 64;

    const uint32_t uA = sptr(sA);
    const uint32_t uW = sptr(sW);
    const int offA = ((lane & 7) + ((lane >> 3) & 1) * 8) * 80 + (lane >> 4) * 16;
    const int offW = ((lane & 7) + ((lane >> 3) & 1) * 8) * 144 + (lane >> 4) * 16;

    float acc[2][4][4] = {};

    for (int kt = 0; kt < K; kt += 32) {
        #pragma unroll
        for (int t = 0; t < 8; t++) {
            int idx = tid + t * 256;
            int i = idx >> 4, k2 = idx & 15;
            int m = row0 + i;
            int bb = m / rowsPerBatch;
            int r = m - bb * rowsPerBatch;
            size_t arow = (size_t)(bb * aBatchStride + aSeqOff + r) * K + kt + 2 * k2;
            if (AHALF) {
                ((__half2*)sA)[i * 20 + k2] = *(const __half2*)((const __half*)Ap + arow);
            } else {
                float2 v = *(const float2*)((const float*)Ap + arow);
                ((__half2*)sA)[i * 20 + k2] = __floats2half2_rn(v.x, v.y);
            }
        }
        #pragma unroll
        for (int t = 0; t < 4; t++) {
            int idx = tid + t * 256;
            int kr = idx >> 5, n2 = idx & 31;
            float2 v = *(const float2*)&W[(size_t)(kt + kr) * Ncols + col0 + 2 * n2];
            ((__half2*)sW)[kr * 36 + n2] = __floats2half2_rn(v.x, v.y);
        }
        __syncthreads();

        #pragma unroll
        for (int kk = 0; kk < 2; kk++) {
            uint32_t a[2][4];
            #pragma unroll
            for (int mt = 0; mt < 2; mt++)
                ldsm_x4(a[mt][0], a[mt][1], a[mt][2], a[mt][3],
                        uA + (wy * 32 + mt * 16) * 80 + kk * 32 + offA);
            #pragma unroll
            for (int p = 0; p < 2; p++) {
                uint32_t b0, b1, b2, b3;
                ldsm_x4_t(b0, b1, b2, b3,
                          uW + kk * 16 * 144 + (wx * 32 + p * 16) * 2 + offW);
                mma_f16(acc[0][2 * p],     a[0][0], a[0][1], a[0][2], a[0][3], b0, b1);
                mma_f16(acc[0][2 * p + 1], a[0][0], a[0][1], a[0][2], a[0][3], b2, b3);
                mma_f16(acc[1][2 * p],     a[1][0], a[1][1], a[1][2], a[1][3], b0, b1);
                mma_f16(acc[1][2 * p + 1], a[1][0], a[1][1], a[1][2], a[1][3], b2, b3);
            }
        }
        __syncthreads();
    }

    #pragma unroll
    for (int mt = 0; mt < 2; mt++) {
        #pragma unroll
        for (int hh = 0; hh < 2; hh++) {
            int m = row0 + wy * 32 + mt * 16 + g + 8 * hh;
            int bb = m / rowsPerBatch;
            int r = m - bb * rowsPerBatch;
            #pragma unroll
            for (int n = 0; n < 4; n++) {
                int c = col0 + wx * 32 + n * 8 + 2 * qd;
                float v0 = (acc[mt][n][hh * 2 + 0] + bias[c]) * scl;
                float v1 = (acc[mt][n][hh * 2 + 1] + bias[c + 1]) * scl;
                if (dstMode == 0) {
                    int hidx = c >> 6, d = c & 63;
                    __half* dh = (__half*)dst;
                    *(__half2*)&dh[((size_t)(bb * HEADS + hidx) * LTOT +
                                    dstSeqOff + r) * DHEAD + d] = __floats2half2_rn(v0, v1);
                } else {
                    float* df = (float*)dst;
                    *(float2*)&df[(size_t)m * Ncols + c] = make_float2(v0, v1);
                }
            }
        }
    }
}

// ---------------------------------------------------------------------------
// Flash attention over compacted rows as BOTH queries and keys (the mask is
// shared between them in the reference). CTAs with q0 >= nk exit immediately
// (~12 of 24 q-tiles active -> single wave). Output scattered to row kidx[q].
// Masked rows of g_oh are written by patch_kernel (uniform softmax = Vmean).
// ---------------------------------------------------------------------------
#define KVSTR 72
#define KVBUF_H (64 * KVSTR)
#define KVBUF_B (KVBUF_H * 2)
#define ATTN_SMEM_BYTES (4 * KVBUF_B)

__global__ __launch_bounds__(256, 2) void attn_f16_kernel() {
    const int b = blockIdx.y >> 3;
    const int nk = g_nk[b];
    const int q0 = blockIdx.x * 128;
    if (q0 >= nk) return;

    extern __shared__ __align__(16) char smraw[];
    __half* Kh = (__half*)smraw;                 // [2][64][72]
    __half* Vh = (__half*)(smraw + 2 * KVBUF_B); // [2][64][72]

    const int tid = threadIdx.x;
    const int warp = tid >> 5, lane = tid & 31;
    const int g = lane >> 2, qd = lane & 3;
    const int bh = blockIdx.y, h = bh & 7;

    const __half* Qg = g_qh + (size_t)bh * LTOT * DHEAD;
    const __half* Kg = g_kh + (size_t)bh * LTOT * DHEAD;
    const __half* Vg = g_vh + (size_t)bh * LTOT * DHEAD;
    const int* kidx = g_kidx + b * LTOT;
    const int NIT = (nk + 63) >> 6;

    const uint32_t uK = sptr(Kh), uV = sptr(Vh);
    const int offA = ((lane & 7) + ((lane >> 3) & 1) * 8) * 144 + (lane >> 4) * 16;
    const int offK = ((lane & 7) + ((lane >> 4) & 1) * 8) * 144 + ((lane >> 3) & 1) * 16;

    const int prow = tid >> 3;                   // 0..31
    const int pch = (tid & 7) * 16;              // byte offset 0..112

    // Prologue: gather-load tile 0
    {
        #pragma unroll
        for (int rr = 0; rr < 2; rr++) {
            int r = prow + rr * 32;
            int idx = (r < nk) ? kidx[r] : 0;
            cp16(uK + r * 144 + pch, Kg + (size_t)idx * 64 + (pch >> 1));
            cp16(uV + r * 144 + pch, Vg + (size_t)idx * 64 + (pch >> 1));
        }
        cp_commit();
    }

    // Query rows (gathered): this thread's two row indices + validity
    const int qr_a = q0 + warp * 16 + g;
    const int qr_b = qr_a + 8;
    const int valid0 = qr_a < nk;
    const int valid1 = qr_b < nk;
    const int qi0 = valid0 ? kidx[qr_a] : kidx[0];
    const int qi1 = valid1 ? kidx[qr_b] : kidx[0];

    // Q fragments, register-resident (pre-scaled by SCALE*LOG2E in gmem)
    uint32_t qa[4][4];
    {
        const __half* qr0p = Qg + (size_t)qi0 * DHEAD;
        const __half* qr1p = Qg + (size_t)qi1 * DHEAD;
        #pragma unroll
        for (int kk = 0; kk < 4; kk++) {
            int c = kk * 16 + 2 * qd;
            qa[kk][0] = *(const uint32_t*)(qr0p + c);
            qa[kk][1] = *(const uint32_t*)(qr1p + c);
            qa[kk][2] = *(const uint32_t*)(qr0p + c + 8);
            qa[kk][3] = *(const uint32_t*)(qr1p + c + 8);
        }
    }

    float m_i[2] = {-FLT_MAX, -FLT_MAX};
    float l_i[2] = {0.f, 0.f};
    float o[8][4] = {};

    for (int it = 0; it < NIT; it++) {
        const int bf = it & 1;
        const int k0 = it * 64;
        cp_wait0();
        __syncthreads();

        if (it + 1 < NIT) {
            uint32_t uKn = uK + (bf ^ 1) * KVBUF_B;
            uint32_t uVn = uV + (bf ^ 1) * KVBUF_B;
            #pragma unroll
            for (int rr = 0; rr < 2; rr++) {
                int r = prow + rr * 32;
                int gi = k0 + 64 + r;
                int idx = (gi < nk) ? kidx[gi] : 0;
                cp16(uKn + r * 144 + pch, Kg + (size_t)idx * 64 + (pch >> 1));
                cp16(uVn + r * 144 + pch, Vg + (size_t)idx * 64 + (pch >> 1));
            }
            cp_commit();
        }

        const uint32_t uKb = uK + bf * KVBUF_B;
        const uint32_t uVb = uV + bf * KVBUF_B;

        // ---- S = Q @ K^T ----
        float s[8][4] = {};
        #pragma unroll
        for (int kk = 0; kk < 4; kk++) {
            #pragma unroll
            for (int p = 0; p < 4; p++) {
                uint32_t b0, b1, b2, b3;
                ldsm_x4(b0, b1, b2, b3, uKb + p * 16 * 144 + kk * 32 + offK);
                mma_f16(s[2 * p],     qa[kk][0], qa[kk][1], qa[kk][2], qa[kk][3], b0, b1);
                mma_f16(s[2 * p + 1], qa[kk][0], qa[kk][1], qa[kk][2], qa[kk][3], b2, b3);
            }
        }

        // ---- tail masking (key side) ----
        if (k0 + 64 > nk) {
            #pragma unroll
            for (int nt = 0; nt < 8; nt++) {
                int j0 = k0 + nt * 8 + 2 * qd;
                if (j0 >= nk)     { s[nt][0] = -FLT_MAX; s[nt][2] = -FLT_MAX; }
                if (j0 + 1 >= nk) { s[nt][1] = -FLT_MAX; s[nt][3] = -FLT_MAX; }
            }
        }

        // ---- online softmax (base-2) ----
        #pragma unroll
        for (int hh = 0; hh < 2; hh++) {
            float mx = -FLT_MAX;
            #pragma unroll
            for (int nt = 0; nt < 8; nt++)
                mx = fmaxf(mx, fmaxf(s[nt][hh * 2], s[nt][hh * 2 + 1]));
            mx = fmaxf(mx, __shfl_xor_sync(0xffffffffu, mx, 1));
            mx = fmaxf(mx, __shfl_xor_sync(0xffffffffu, mx, 2));
            float mnew = fmaxf(m_i[hh], mx);
            float corr = fexp2(m_i[hh] - mnew);
            m_i[hh] = mnew;
            float rs = 0.f;
            #pragma unroll
            for (int nt = 0; nt < 8; nt++) {
                float p0 = fexp2(s[nt][hh * 2]     - mnew);
                float p1 = fexp2(s[nt][hh * 2 + 1] - mnew);
                rs += p0 + p1;
                s[nt][hh * 2]     = p0;
                s[nt][hh * 2 + 1] = p1;
            }
            rs += __shfl_xor_sync(0xffffffffu, rs, 1);
            rs += __shfl_xor_sync(0xffffffffu, rs, 2);
            l_i[hh] = l_i[hh] * corr + rs;
            #pragma unroll
            for (int nt = 0; nt < 8; nt++) {
                o[nt][hh * 2]     *= corr;
                o[nt][hh * 2 + 1] *= corr;
            }
        }

        // ---- O += P @ V (P in registers; C-frag == A-frag layout) ----
        #pragma unroll
        for (int jj = 0; jj < 4; jj++) {
            uint32_t pa0 = packh2(s[2 * jj][0],     s[2 * jj][1]);
            uint32_t pa1 = packh2(s[2 * jj][2],     s[2 * jj][3]);
            uint32_t pa2 = packh2(s[2 * jj + 1][0], s[2 * jj + 1][1]);
            uint32_t pa3 = packh2(s[2 * jj + 1][2], s[2 * jj + 1][3]);
            #pragma unroll
            for (int p = 0; p < 4; p++) {
                uint32_t b0, b1, b2, b3;
                ldsm_x4_t(b0, b1, b2, b3, uVb + jj * 16 * 144 + p * 32 + offA);
                mma_f16(o[2 * p],     pa0, pa1, pa2, pa3, b0, b1);
                mma_f16(o[2 * p + 1], pa0, pa1, pa2, pa3, b2, b3);
            }
        }
    }

    // ---- epilogue: normalize + scatter to original row indices ----
    #pragma unroll
    for (int hh = 0; hh < 2; hh++) {
        if (!(hh ? valid1 : valid0)) continue;
        const int qrow = hh ? qi1 : qi0;
        float inv = 1.f / l_i[hh];
        __half* dstp = &g_oh[(size_t)(b * LTOT + qrow) * INNER + h * DHEAD];
        #pragma unroll
        for (int nt = 0; nt < 8; nt++) {
            int d0 = nt * 8 + 2 * qd;
            *(__half2*)&dstp[d0] =
                __floats2half2_rn(o[nt][hh * 2] * inv, o[nt][hh * 2 + 1] * inv);
        }
    }
}

// ---------------------------------------------------------------------------
// kernel_launch
// ---------------------------------------------------------------------------
extern "C" void kernel_launch(void* const* d_in, const int* in_sizes, int n_in,
                              void* d_out, int out_size) {
    const float* nodes = (const float*)d_in[0];
    const float* edges = (const float*)d_in[1];
    const unsigned char* mask_raw = (const unsigned char*)d_in[2];
    const float* Wq  = (const float*)d_in[3];
    const float* bq  = (const float*)d_in[4];
    const float* Wk  = (const float*)d_in[5];
    const float* bk  = (const float*)d_in[6];
    const float* Wv  = (const float*)d_in[7];
    const float* bv  = (const float*)d_in[8];
    const float* Weq = (const float*)d_in[9];
    const float* beq = (const float*)d_in[10];
    const float* Wek = (const float*)d_in[11];
    const float* bek = (const float*)d_in[12];
    const float* Wev = (const float*)d_in[13];
    const float* bev = (const float*)d_in[14];
    const float* Wo  = (const float*)d_in[15];
    const float* bo  = (const float*)d_in[16];
    const float* Weo = (const float*)d_in[17];
    const float* beo = (const float*)d_in[18];
    float* out = (float*)d_out;

    void *qp, *kp, *vp, *op;
    cudaGetSymbolAddress(&qp, g_qh);
    cudaGetSymbolAddress(&kp, g_kh);
    cudaGetSymbolAddress(&vp, g_vh);
    cudaGetSymbolAddress(&op, g_oh);

    mask_kernel<<<BSZ, 256>>>(mask_raw);

    const float qscale = SCALE * LOG2E;

    // Node Q/K/V projections fused (z): M=2048, K=128, N=512
    gemm_f16_kernel<false><<<dim3(8, 16, 3), 256>>>(
        nodes, Wq, Wk, Wv, bq, bk, bv, qp, kp, vp,
        qscale, 1.f, 1.f, 2048, 128, 512, 1024, 1024, 0, 0, 0);

    // Edge Q/K/V projections fused: M=4096, K=256, N=512, seq offset 1024
    gemm_f16_kernel<false><<<dim3(8, 32, 3), 256>>>(
        edges, Weq, Wek, Wev, beq, bek, bev, qp, kp, vp,
        qscale, 1.f, 1.f, 4096, 256, 512, 2048, 2048, 0, 0, 1024);

    // Partial V sums per (b,h)
    vmean_kernel<<<BSZ * HEADS * NCH, 256>>>();

    // Flash attention over compacted queries x compacted keys
    cudaFuncSetAttribute(attn_f16_kernel,
                         cudaFuncAttributeMaxDynamicSharedMemorySize, ATTN_SMEM_BYTES);
    attn_f16_kernel<<<dim3(LTOT / 128, BSZ * HEADS), 256, ATTN_SMEM_BYTES>>>();

    // Patch masked rows with uniform-softmax result (Vmean)
    patch_kernel<<<96, 256>>>();

    // Output projections
    gemm_f16_kernel<true><<<dim3(2, 16, 1), 256>>>(
        op, Wo, Wo, Wo, bo, bo, bo, out, out, out,
        1.f, 1.f, 1.f, 2048, 512, 128, 1024, 3072, 0, 1, 0);
    gemm_f16_kernel<true><<<dim3(4, 32, 1), 256>>>(
        op, Weo, Weo, Weo, beo, beo, beo,
        out + 2 * 1024 * 128, out + 2 * 1024 * 128, out + 2 * 1024 * 128,
        1.f, 1.f, 1.f, 4096, 512, 256, 2048, 3072, 1024, 1, 0);
}

// round 8
// speedup vs baseline: 14.0130x; 1.1997x over previous
#include <cuda_runtime.h>
#include <cuda_fp16.h>
#include <float.h>
#include <math.h>
#include <stdint.h>

// Problem constants
#define BSZ   2
#define NN    1024
#define EE    2048
#define LTOT  3072
#define HEADS 8
#define DHEAD 64
#define INNER 512
#define SCALE 0.125f
#define LOG2E 1.4426950408889634f
#define NCH   16                                // vmean chunks per (b,h)

// Scratch (fp16 intermediates)
__device__ __half g_qh[BSZ * HEADS * LTOT * DHEAD];   // pre-scaled by SCALE*LOG2E
__device__ __half g_kh[BSZ * HEADS * LTOT * DHEAD];
__device__ __half g_vh[BSZ * HEADS * LTOT * DHEAD];
__device__ __half g_oh[BSZ * LTOT * INNER];
__device__ int    g_mask[BSZ * LTOT];
__device__ int    g_kidx[BSZ * LTOT];                 // compacted unmasked indices
__device__ int    g_nk[BSZ];
__device__ float  g_vpart[BSZ * HEADS * NCH * DHEAD]; // partial V sums

// ---------------------------------------------------------------------------
// PTX helpers
// ---------------------------------------------------------------------------
__device__ __forceinline__ uint32_t sptr(const void* p) {
    return (uint32_t)__cvta_generic_to_shared(p);
}
__device__ __forceinline__ void ldsm_x4(uint32_t& r0, uint32_t& r1,
                                        uint32_t& r2, uint32_t& r3, uint32_t addr) {
    asm volatile("ldmatrix.sync.aligned.m8n8.x4.shared.b16 {%0,%1,%2,%3}, [%4];"
                 : "=r"(r0), "=r"(r1), "=r"(r2), "=r"(r3) : "r"(addr));
}
__device__ __forceinline__ void ldsm_x4_t(uint32_t& r0, uint32_t& r1,
                                          uint32_t& r2, uint32_t& r3, uint32_t addr) {
    asm volatile("ldmatrix.sync.aligned.m8n8.x4.trans.shared.b16 {%0,%1,%2,%3}, [%4];"
                 : "=r"(r0), "=r"(r1), "=r"(r2), "=r"(r3) : "r"(addr));
}
__device__ __forceinline__ void mma_f16(float c[4],
                                        uint32_t a0, uint32_t a1, uint32_t a2, uint32_t a3,
                                        uint32_t b0, uint32_t b1) {
    asm volatile(
        "mma.sync.aligned.m16n8k16.row.col.f32.f16.f16.f32 "
        "{%0,%1,%2,%3}, {%4,%5,%6,%7}, {%8,%9}, {%0,%1,%2,%3};"
        : "+f"(c[0]), "+f"(c[1]), "+f"(c[2]), "+f"(c[3])
        : "r"(a0), "r"(a1), "r"(a2), "r"(a3), "r"(b0), "r"(b1));
}
__device__ __forceinline__ void cp16(uint32_t dst, const void* src) {
    asm volatile("cp.async.cg.shared.global [%0], [%1], 16;" :: "r"(dst), "l"(src));
}
__device__ __forceinline__ void cp_commit() {
    asm volatile("cp.async.commit_group;");
}
__device__ __forceinline__ void cp_wait0() {
    asm volatile("cp.async.wait_group 0;");
}
__device__ __forceinline__ uint32_t packh2(float x, float y) {
    __half2 h = __floats2half2_rn(x, y);
    return *reinterpret_cast<uint32_t*>(&h);
}
__device__ __forceinline__ float fexp2(float x) {
    float y;
    asm("ex2.approx.ftz.f32 %0, %1;" : "=f"(y) : "f"(x));
    return y;
}

// ---------------------------------------------------------------------------
// Mask decode + per-batch compaction of unmasked indices.
// ---------------------------------------------------------------------------
__global__ void mask_kernel(const unsigned char* __restrict__ raw) {
    __shared__ int partial[256];
    __shared__ int pfx[256];
    const int n = BSZ * LTOT;
    const int b = blockIdx.x;
    const int tid = threadIdx.x;

    int cnt = 0;
    for (int i = tid; i < n; i += 256) cnt += (raw[i] != 0);
    partial[tid] = cnt;
    __syncthreads();
    for (int s = 128; s > 0; s >>= 1) {
        if (tid < s) partial[tid] += partial[tid + s];
        __syncthreads();
    }
    const int width1 = partial[0] > (n * 3 / 8);
    const int* raw32 = (const int*)raw;

    int bits[12];
    int myc = 0;
    #pragma unroll
    for (int i = 0; i < 12; i++) {
        int li = tid * 12 + i;
        int gi = b * LTOT + li;
        int v = width1 ? (raw[gi] != 0) : (raw32[gi] != 0);
        g_mask[gi] = v;
        bits[i] = v;
        myc += v;
    }
    pfx[tid] = myc;
    __syncthreads();
    if (tid == 0) {
        int acc = 0;
        for (int t = 0; t < 256; t++) { int c = pfx[t]; pfx[t] = acc; acc += c; }
        g_nk[b] = acc;
    }
    __syncthreads();
    int off = b * LTOT + pfx[tid];
    #pragma unroll
    for (int i = 0; i < 12; i++)
        if (bits[i]) g_kidx[off++] = tid * 12 + i;
}

// ---------------------------------------------------------------------------
// Partial V sums: grid = BSZ*HEADS*NCH (chunks of LTOT/NCH = 192 rows).
// ---------------------------------------------------------------------------
__global__ void vmean_kernel() {
    const int bh = blockIdx.x / NCH;
    const int chunk = blockIdx.x % NCH;
    const int CROWS = LTOT / NCH;                // 192
    const __half* Vg = g_vh + (size_t)bh * LTOT * DHEAD + (size_t)chunk * CROWS * DHEAD;
    const int tid = threadIdx.x;
    const int rg = tid >> 3;           // 0..31 row group
    const int dg = tid & 7;            // covers d = dg*8 .. dg*8+7

    float acc[8] = {};
    for (int r = rg; r < CROWS; r += 32) {
        uint4 u = *(const uint4*)(Vg + (size_t)r * DHEAD + dg * 8);
        const __half2* h2 = (const __half2*)&u;
        #pragma unroll
        for (int j = 0; j < 4; j++) {
            float2 f = __half22float2(h2[j]);
            acc[2 * j]     += f.x;
            acc[2 * j + 1] += f.y;
        }
    }

    __shared__ float sm[256][8];
    #pragma unroll
    for (int j = 0; j < 8; j++) sm[tid][j] = acc[j];
    __syncthreads();

    if (tid < DHEAD) {
        int d = tid;
        int srcdg = d >> 3, j = d & 7;
        float s = 0.f;
        #pragma unroll
        for (int r = 0; r < 32; r++) s += sm[srcdg + 8 * r][j];
        g_vpart[(bh * NCH + chunk) * DHEAD + d] = s;
    }
}

// ---------------------------------------------------------------------------
// GEMM body (device fn): C = (A' @ W + bias) * scale, 128x64 tile, BK=32,
// 256 threads = 8 warps (4x2), warp tile 32x32. AHALF: A fp16 else fp32.
// DSTMODE 0: scatter fp16 into [B,H,L,D]; 1: fp32 [m, Ncols].
// ---------------------------------------------------------------------------
template <bool AHALF, int DSTMODE>
__device__ __forceinline__ void gemm_body(
        const void* __restrict__ Ap, const float* __restrict__ W,
        const float* __restrict__ bias, void* __restrict__ dst, float scl,
        int K, int Ncols, int rowsPerBatch, int aBatchStride, int aSeqOff,
        int dstSeqOff, int row0, int col0) {
    __shared__ __align__(16) __half sA[128 * 40];
    __shared__ __align__(16) __half sW[32 * 72];

    const int tid = threadIdx.x;
    const int warp = tid >> 5, lane = tid & 31;
    const int g = lane >> 2, qd = lane & 3;
    const int wy = warp >> 1, wx = warp & 1;

    const uint32_t uA = sptr(sA);
    const uint32_t uW = sptr(sW);
    const int offA = ((lane & 7) + ((lane >> 3) & 1) * 8) * 80 + (lane >> 4) * 16;
    const int offW = ((lane & 7) + ((lane >> 3) & 1) * 8) * 144 + (lane >> 4) * 16;

    float acc[2][4][4] = {};

    for (int kt = 0; kt < K; kt += 32) {
        #pragma unroll
        for (int t = 0; t < 8; t++) {
            int idx = tid + t * 256;
            int i = idx >> 4, k2 = idx & 15;
            int m = row0 + i;
            int bb = m / rowsPerBatch;
            int r = m - bb * rowsPerBatch;
            size_t arow = (size_t)(bb * aBatchStride + aSeqOff + r) * K + kt + 2 * k2;
            if (AHALF) {
                ((__half2*)sA)[i * 20 + k2] = *(const __half2*)((const __half*)Ap + arow);
            } else {
                float2 v = *(const float2*)((const float*)Ap + arow);
                ((__half2*)sA)[i * 20 + k2] = __floats2half2_rn(v.x, v.y);
            }
        }
        #pragma unroll
        for (int t = 0; t < 4; t++) {
            int idx = tid + t * 256;
            int kr = idx >> 5, n2 = idx & 31;
            float2 v = *(const float2*)&W[(size_t)(kt + kr) * Ncols + col0 + 2 * n2];
            ((__half2*)sW)[kr * 36 + n2] = __floats2half2_rn(v.x, v.y);
        }
        __syncthreads();

        #pragma unroll
        for (int kk = 0; kk < 2; kk++) {
            uint32_t a[2][4];
            #pragma unroll
            for (int mt = 0; mt < 2; mt++)
                ldsm_x4(a[mt][0], a[mt][1], a[mt][2], a[mt][3],
                        uA + (wy * 32 + mt * 16) * 80 + kk * 32 + offA);
            #pragma unroll
            for (int p = 0; p < 2; p++) {
                uint32_t b0, b1, b2, b3;
                ldsm_x4_t(b0, b1, b2, b3,
                          uW + kk * 16 * 144 + (wx * 32 + p * 16) * 2 + offW);
                mma_f16(acc[0][2 * p],     a[0][0], a[0][1], a[0][2], a[0][3], b0, b1);
                mma_f16(acc[0][2 * p + 1], a[0][0], a[0][1], a[0][2], a[0][3], b2, b3);
                mma_f16(acc[1][2 * p],     a[1][0], a[1][1], a[1][2], a[1][3], b0, b1);
                mma_f16(acc[1][2 * p + 1], a[1][0], a[1][1], a[1][2], a[1][3], b2, b3);
            }
        }
        __syncthreads();
    }

    #pragma unroll
    for (int mt = 0; mt < 2; mt++) {
        #pragma unroll
        for (int hh = 0; hh < 2; hh++) {
            int m = row0 + wy * 32 + mt * 16 + g + 8 * hh;
            int bb = m / rowsPerBatch;
            int r = m - bb * rowsPerBatch;
            #pragma unroll
            for (int n = 0; n < 4; n++) {
                int c = col0 + wx * 32 + n * 8 + 2 * qd;
                float v0 = (acc[mt][n][hh * 2 + 0] + bias[c]) * scl;
                float v1 = (acc[mt][n][hh * 2 + 1] + bias[c + 1]) * scl;
                if (DSTMODE == 0) {
                    int hidx = c >> 6, d = c & 63;
                    __half* dh = (__half*)dst;
                    *(__half2*)&dh[((size_t)(bb * HEADS + hidx) * LTOT +
                                    dstSeqOff + r) * DHEAD + d] = __floats2half2_rn(v0, v1);
                } else {
                    float* df = (float*)dst;
                    *(float2*)&df[(size_t)m * Ncols + c] = make_float2(v0, v1);
                }
            }
        }
    }
}

// ---------------------------------------------------------------------------
// Fused QKV projections (node + edge, all six GEMMs) in one launch.
// 1D grid of 1152 CTAs: [0,384) node {z=Q,K,V}x(8x16 tiles), [384,1152) edge.
// ---------------------------------------------------------------------------
__global__ __launch_bounds__(256) void qkv_kernel(
        const float* __restrict__ nodes, const float* __restrict__ edges,
        const float* Wq, const float* Wk, const float* Wv,
        const float* bq, const float* bk, const float* bv,
        const float* Weq, const float* Wek, const float* Wev,
        const float* beq, const float* bek, const float* bev,
        __half* qp, __half* kp, __half* vp, float qscale) {
    const int t = blockIdx.x;
    if (t < 384) {
        const int z = t / 128, r = t % 128;
        const int col0 = (r & 7) * 64, row0 = (r >> 3) * 128;
        const float* W    = (z == 0) ? Wq : (z == 1) ? Wk : Wv;
        const float* bias = (z == 0) ? bq : (z == 1) ? bk : bv;
        __half* dst       = (z == 0) ? qp : (z == 1) ? kp : vp;
        const float scl   = (z == 0) ? qscale : 1.f;
        gemm_body<false, 0>(nodes, W, bias, dst, scl,
                            128, 512, 1024, 1024, 0, 0, row0, col0);
    } else {
        const int u = t - 384;
        const int z = u / 256, r = u % 256;
        const int col0 = (r & 7) * 64, row0 = (r >> 3) * 128;
        const float* W    = (z == 0) ? Weq : (z == 1) ? Wek : Wev;
        const float* bias = (z == 0) ? beq : (z == 1) ? bek : bev;
        __half* dst       = (z == 0) ? qp : (z == 1) ? kp : vp;
        const float scl   = (z == 0) ? qscale : 1.f;
        gemm_body<false, 0>(edges, W, bias, dst, scl,
                            256, 512, 2048, 2048, 0, 1024, row0, col0);
    }
}

// ---------------------------------------------------------------------------
// Fused output projections (node + edge) in one launch. 160 CTAs:
// [0,32) node (2x16 tiles), [32,160) edge (4x32 tiles).
// ---------------------------------------------------------------------------
__global__ __launch_bounds__(256) void outproj_kernel(
        const float* __restrict__ Wo, const float* __restrict__ bo,
        const float* __restrict__ Weo, const float* __restrict__ beo,
        float* __restrict__ out) {
    const int t = blockIdx.x;
    if (t < 32) {
        const int col0 = (t & 1) * 64, row0 = (t >> 1) * 128;
        gemm_body<true, 1>(g_oh, Wo, bo, out, 1.f,
                           512, 128, 1024, 3072, 0, 0, row0, col0);
    } else {
        const int u = t - 32;
        const int col0 = (u & 3) * 64, row0 = (u >> 2) * 128;
        gemm_body<true, 1>(g_oh, Weo, beo, out + 2 * 1024 * 128, 1.f,
                           512, 256, 2048, 3072, 1024, 0, row0, col0);
    }
}

// ---------------------------------------------------------------------------
// Flash attention over compacted rows (queries AND keys). Idle CTAs
// (q0 >= nk) patch masked rows of g_oh with the uniform-softmax result
// (mean of V over ALL keys, from g_vpart). Disjoint row sets -> no race.
// ---------------------------------------------------------------------------
#define KVSTR 72
#define KVBUF_H (64 * KVSTR)
#define KVBUF_B (KVBUF_H * 2)
#define ATTN_SMEM_BYTES (4 * KVBUF_B)

__device__ __forceinline__ void patch_tiles(int b, int h, int bh, int pstart, int pstep) {
    __shared__ float vms[64];
    const int tid = threadIdx.x;
    if (tid < 64) {
        float s = 0.f;
        #pragma unroll
        for (int c = 0; c < NCH; c++) s += g_vpart[(bh * NCH + c) * DHEAD + tid];
        vms[tid] = s * (1.0f / LTOT);
    }
    __syncthreads();
    const int dg = tid & 7;
    uint4 hv;
    hv.x = packh2(vms[dg * 8 + 0], vms[dg * 8 + 1]);
    hv.y = packh2(vms[dg * 8 + 2], vms[dg * 8 + 3]);
    hv.z = packh2(vms[dg * 8 + 4], vms[dg * 8 + 5]);
    hv.w = packh2(vms[dg * 8 + 6], vms[dg * 8 + 7]);
    for (int p = pstart; p < 24; p += pstep) {
        #pragma unroll
        for (int pass = 0; pass < 4; pass++) {
            int r = p * 128 + pass * 32 + (tid >> 3);
            if (!g_mask[b * LTOT + r])
                *(uint4*)&g_oh[(size_t)(b * LTOT + r) * INNER + h * DHEAD + dg * 8] = hv;
        }
    }
}

__global__ __launch_bounds__(256, 2) void attn_f16_kernel() {
    const int bh = blockIdx.y;
    const int b = bh >> 3, h = bh & 7;
    const int nk = g_nk[b];
    const int q0 = blockIdx.x * 128;
    const int qtiles = (nk + 127) >> 7;
    const int nidle = 24 - qtiles;

    if (q0 >= nk) {
        // Idle CTA: patch masked rows. Covers all 24 row-tiles across idles.
        patch_tiles(b, h, bh, blockIdx.x - qtiles, nidle);
        return;
    }

    extern __shared__ __align__(16) char smraw[];
    __half* Kh = (__half*)smraw;                 // [2][64][72]
    __half* Vh = (__half*)(smraw + 2 * KVBUF_B); // [2][64][72]

    const int tid = threadIdx.x;
    const int warp = tid >> 5, lane = tid & 31;
    const int g = lane >> 2, qd = lane & 3;

    const __half* Qg = g_qh + (size_t)bh * LTOT * DHEAD;
    const __half* Kg = g_kh + (size_t)bh * LTOT * DHEAD;
    const __half* Vg = g_vh + (size_t)bh * LTOT * DHEAD;
    const int* kidx = g_kidx + b * LTOT;
    const int NIT = (nk + 63) >> 6;

    const uint32_t uK = sptr(Kh), uV = sptr(Vh);
    const int offA = ((lane & 7) + ((lane >> 3) & 1) * 8) * 144 + (lane >> 4) * 16;
    const int offK = ((lane & 7) + ((lane >> 4) & 1) * 8) * 144 + ((lane >> 3) & 1) * 16;

    const int prow = tid >> 3;                   // 0..31
    const int pch = (tid & 7) * 16;              // byte offset 0..112

    // Prologue: gather-load tile 0
    {
        #pragma unroll
        for (int rr = 0; rr < 2; rr++) {
            int r = prow + rr * 32;
            int idx = (r < nk) ? kidx[r] : 0;
            cp16(uK + r * 144 + pch, Kg + (size_t)idx * 64 + (pch >> 1));
            cp16(uV + r * 144 + pch, Vg + (size_t)idx * 64 + (pch >> 1));
        }
        cp_commit();
    }

    // Query rows (gathered)
    const int qr_a = q0 + warp * 16 + g;
    const int qr_b = qr_a + 8;
    const int valid0 = qr_a < nk;
    const int valid1 = qr_b < nk;
    const int qi0 = valid0 ? kidx[qr_a] : kidx[0];
    const int qi1 = valid1 ? kidx[qr_b] : kidx[0];

    uint32_t qa[4][4];
    {
        const __half* qr0p = Qg + (size_t)qi0 * DHEAD;
        const __half* qr1p = Qg + (size_t)qi1 * DHEAD;
        #pragma unroll
        for (int kk = 0; kk < 4; kk++) {
            int c = kk * 16 + 2 * qd;
            qa[kk][0] = *(const uint32_t*)(qr0p + c);
            qa[kk][1] = *(const uint32_t*)(qr1p + c);
            qa[kk][2] = *(const uint32_t*)(qr0p + c + 8);
            qa[kk][3] = *(const uint32_t*)(qr1p + c + 8);
        }
    }

    float m_i[2] = {-FLT_MAX, -FLT_MAX};
    float l_i[2] = {0.f, 0.f};
    float o[8][4] = {};

    for (int it = 0; it < NIT; it++) {
        const int bf = it & 1;
        const int k0 = it * 64;
        cp_wait0();
        __syncthreads();

        if (it + 1 < NIT) {
            uint32_t uKn = uK + (bf ^ 1) * KVBUF_B;
            uint32_t uVn = uV + (bf ^ 1) * KVBUF_B;
            #pragma unroll
            for (int rr = 0; rr < 2; rr++) {
                int r = prow + rr * 32;
                int gi = k0 + 64 + r;
                int idx = (gi < nk) ? kidx[gi] : 0;
                cp16(uKn + r * 144 + pch, Kg + (size_t)idx * 64 + (pch >> 1));
                cp16(uVn + r * 144 + pch, Vg + (size_t)idx * 64 + (pch >> 1));
            }
            cp_commit();
        }

        const uint32_t uKb = uK + bf * KVBUF_B;
        const uint32_t uVb = uV + bf * KVBUF_B;

        // ---- S = Q @ K^T ----
        float s[8][4] = {};
        #pragma unroll
        for (int kk = 0; kk < 4; kk++) {
            #pragma unroll
            for (int p = 0; p < 4; p++) {
                uint32_t b0, b1, b2, b3;
                ldsm_x4(b0, b1, b2, b3, uKb + p * 16 * 144 + kk * 32 + offK);
                mma_f16(s[2 * p],     qa[kk][0], qa[kk][1], qa[kk][2], qa[kk][3], b0, b1);
                mma_f16(s[2 * p + 1], qa[kk][0], qa[kk][1], qa[kk][2], qa[kk][3], b2, b3);
            }
        }

        // ---- tail masking (key side) ----
        if (k0 + 64 > nk) {
            #pragma unroll
            for (int nt = 0; nt < 8; nt++) {
                int j0 = k0 + nt * 8 + 2 * qd;
                if (j0 >= nk)     { s[nt][0] = -FLT_MAX; s[nt][2] = -FLT_MAX; }
                if (j0 + 1 >= nk) { s[nt][1] = -FLT_MAX; s[nt][3] = -FLT_MAX; }
            }
        }

        // ---- online softmax (base-2) ----
        #pragma unroll
        for (int hh = 0; hh < 2; hh++) {
            float mx = -FLT_MAX;
            #pragma unroll
            for (int nt = 0; nt < 8; nt++)
                mx = fmaxf(mx, fmaxf(s[nt][hh * 2], s[nt][hh * 2 + 1]));
            mx = fmaxf(mx, __shfl_xor_sync(0xffffffffu, mx, 1));
            mx = fmaxf(mx, __shfl_xor_sync(0xffffffffu, mx, 2));
            float mnew = fmaxf(m_i[hh], mx);
            float corr = fexp2(m_i[hh] - mnew);
            m_i[hh] = mnew;
            float rs = 0.f;
            #pragma unroll
            for (int nt = 0; nt < 8; nt++) {
                float p0 = fexp2(s[nt][hh * 2]     - mnew);
                float p1 = fexp2(s[nt][hh * 2 + 1] - mnew);
                rs += p0 + p1;
                s[nt][hh * 2]     = p0;
                s[nt][hh * 2 + 1] = p1;
            }
            rs += __shfl_xor_sync(0xffffffffu, rs, 1);
            rs += __shfl_xor_sync(0xffffffffu, rs, 2);
            l_i[hh] = l_i[hh] * corr + rs;
            #pragma unroll
            for (int nt = 0; nt < 8; nt++) {
                o[nt][hh * 2]     *= corr;
                o[nt][hh * 2 + 1] *= corr;
            }
        }

        // ---- O += P @ V ----
        #pragma unroll
        for (int jj = 0; jj < 4; jj++) {
            uint32_t pa0 = packh2(s[2 * jj][0],     s[2 * jj][1]);
            uint32_t pa1 = packh2(s[2 * jj][2],     s[2 * jj][3]);
            uint32_t pa2 = packh2(s[2 * jj + 1][0], s[2 * jj + 1][1]);
            uint32_t pa3 = packh2(s[2 * jj + 1][2], s[2 * jj + 1][3]);
            #pragma unroll
            for (int p = 0; p < 4; p++) {
                uint32_t b0, b1, b2, b3;
                ldsm_x4_t(b0, b1, b2, b3, uVb + jj * 16 * 144 + p * 32 + offA);
                mma_f16(o[2 * p],     pa0, pa1, pa2, pa3, b0, b1);
                mma_f16(o[2 * p + 1], pa0, pa1, pa2, pa3, b2, b3);
            }
        }
    }

    // ---- epilogue: normalize + scatter to original row indices ----
    #pragma unroll
    for (int hh = 0; hh < 2; hh++) {
        if (!(hh ? valid1 : valid0)) continue;
        const int qrow = hh ? qi1 : qi0;
        float inv = 1.f / l_i[hh];
        __half* dstp = &g_oh[(size_t)(b * LTOT + qrow) * INNER + h * DHEAD];
        #pragma unroll
        for (int nt = 0; nt < 8; nt++) {
            int d0 = nt * 8 + 2 * qd;
            *(__half2*)&dstp[d0] =
                __floats2half2_rn(o[nt][hh * 2] * inv, o[nt][hh * 2 + 1] * inv);
        }
    }

    // Fallback: if no idle CTAs exist (nk > 2944), last CTA patches everything.
    if (nidle == 0 && blockIdx.x == 23) {
        __syncthreads();
        patch_tiles(b, h, bh, 0, 1);
    }
}

// ---------------------------------------------------------------------------
// kernel_launch
// ---------------------------------------------------------------------------
extern "C" void kernel_launch(void* const* d_in, const int* in_sizes, int n_in,
                              void* d_out, int out_size) {
    const float* nodes = (const float*)d_in[0];
    const float* edges = (const float*)d_in[1];
    const unsigned char* mask_raw = (const unsigned char*)d_in[2];
    const float* Wq  = (const float*)d_in[3];
    const float* bq  = (const float*)d_in[4];
    const float* Wk  = (const float*)d_in[5];
    const float* bk  = (const float*)d_in[6];
    const float* Wv  = (const float*)d_in[7];
    const float* bv  = (const float*)d_in[8];
    const float* Weq = (const float*)d_in[9];
    const float* beq = (const float*)d_in[10];
    const float* Wek = (const float*)d_in[11];
    const float* bek = (const float*)d_in[12];
    const float* Wev = (const float*)d_in[13];
    const float* bev = (const float*)d_in[14];
    const float* Wo  = (const float*)d_in[15];
    const float* bo  = (const float*)d_in[16];
    const float* Weo = (const float*)d_in[17];
    const float* beo = (const float*)d_in[18];
    float* out = (float*)d_out;

    void *qp, *kp, *vp;
    cudaGetSymbolAddress(&qp, g_qh);
    cudaGetSymbolAddress(&kp, g_kh);
    cudaGetSymbolAddress(&vp, g_vh);

    mask_kernel<<<BSZ, 256>>>(mask_raw);

    // All six QKV projections in one launch
    qkv_kernel<<<1152, 256>>>(
        nodes, edges, Wq, Wk, Wv, bq, bk, bv,
        Weq, Wek, Wev, beq, bek, bev,
        (__half*)qp, (__half*)kp, (__half*)vp, SCALE * LOG2E);

    // Partial V sums per (b,h)
    vmean_kernel<<<BSZ * HEADS * NCH, 256>>>();

    // Flash attention over compacted queries x keys + patch in idle CTAs
    cudaFuncSetAttribute(attn_f16_kernel,
                         cudaFuncAttributeMaxDynamicSharedMemorySize, ATTN_SMEM_BYTES);
    attn_f16_kernel<<<dim3(LTOT / 128, BSZ * HEADS), 256, ATTN_SMEM_BYTES>>>();

    // Both output projections in one launch
    outproj_kernel<<<160, 256>>>(Wo, bo, Weo, beo, out);
}